// round 8
// baseline (speedup 1.0000x reference)
#include <cuda_runtime.h>
#include <math.h>

#define Bn 32
#define Tn 2048
#define Vn 50257
#define Dn 512
#define Hn 512
#define BTn (Bn*Tn)

// ------- scratch (__device__ globals: allocation-free) -------
__device__ float g_x[(size_t)BTn*Dn];   // x, then x2 in place
__device__ float g_q[(size_t)BTn*Dn];   // q, then xin
__device__ float g_k[(size_t)BTn*Dn];   // k, then xzx
__device__ float g_v[(size_t)BTn*Dn];
__device__ float g_g[(size_t)BTn*Dn];
__device__ float g_ks[Bn*Dn];
__device__ float g_kvs[Bn*Dn];
__device__ float g_h[2][Bn*Hn];
__device__ float g_hn[Bn*Hn];
__device__ float g_fT[Hn*Hn];
__device__ float g_dt[Hn];
__device__ float g_tau[Hn];
__device__ unsigned g_barrier;

__global__ void k_init() {
    int i = blockIdx.x * 256 + threadIdx.x;
    if (i < Bn*Hn) { g_h[0][i] = 0.f; g_ks[i] = 0.f; g_kvs[i] = 0.f; }
    if (i == 0) g_barrier = 0u;
}

__global__ void k_embed(const int* __restrict__ ids, const float* __restrict__ emb) {
    int bt = blockIdx.x;
    int id = ids[bt];
    ((float4*)(g_x + (size_t)bt * Dn))[threadIdx.x] =
        ((const float4*)(emb + (size_t)id * Dn))[threadIdx.x];
}

// C[m,n] = act( sum_k X[m,k]*W[n,k] + bias[n] ), X = g_x always.
// 128x128 tile, K-tile 8, 256 thr, 8x8/thread. osel: 0 q,1 k,2 v,3 g.
__global__ __launch_bounds__(256,2) void k_proj(int osel, const float* __restrict__ W,
                                                const float* __restrict__ bias, int act) {
    float* outp = (osel==0)?g_q:(osel==1)?g_k:(osel==2)?g_v:g_g;
    __shared__ float As[8][132];
    __shared__ float Bs[8][132];
    int tid = threadIdx.x;
    int tx = tid & 15, ty = tid >> 4;
    int m0 = blockIdx.x * 128, n0 = blockIdx.y * 128;
    int lrow = tid >> 1, lcol = (tid & 1) * 4;
    const float* Ap = g_x + (size_t)(m0 + lrow) * Dn + lcol;
    const float* Bp = W   + (size_t)(n0 + lrow) * Dn + lcol;
    float acc[8][8];
#pragma unroll
    for (int i = 0; i < 8; i++)
#pragma unroll
        for (int j = 0; j < 8; j++) acc[i][j] = 0.f;
    for (int kt = 0; kt < 64; kt++) {
        float4 av = *(const float4*)(Ap + kt*8);
        float4 bv = *(const float4*)(Bp + kt*8);
        __syncthreads();
        As[lcol+0][lrow]=av.x; As[lcol+1][lrow]=av.y; As[lcol+2][lrow]=av.z; As[lcol+3][lrow]=av.w;
        Bs[lcol+0][lrow]=bv.x; Bs[lcol+1][lrow]=bv.y; Bs[lcol+2][lrow]=bv.z; Bs[lcol+3][lrow]=bv.w;
        __syncthreads();
#pragma unroll
        for (int kk = 0; kk < 8; kk++) {
            float a[8], b[8];
            *(float4*)(a)   = *(const float4*)&As[kk][ty*8];
            *(float4*)(a+4) = *(const float4*)&As[kk][ty*8+4];
            *(float4*)(b)   = *(const float4*)&Bs[kk][tx*8];
            *(float4*)(b+4) = *(const float4*)&Bs[kk][tx*8+4];
#pragma unroll
            for (int i = 0; i < 8; i++)
#pragma unroll
                for (int j = 0; j < 8; j++) acc[i][j] += a[i]*b[j];
        }
    }
#pragma unroll
    for (int i = 0; i < 8; i++) {
        int m = m0 + ty*8 + i;
#pragma unroll
        for (int j = 0; j < 8; j++) {
            int n = n0 + tx*8 + j;
            float c = acc[i][j];
            if (bias) c += bias[n];
            if (act == 1)      c = (c > 0.f) ? (c + 1.f) : __expf(c);  // elu+1
            else if (act == 2) c = 1.f / (1.f + __expf(-c));           // sigmoid
            outp[(size_t)m * Dn + n] = c;
        }
    }
}

// k_sum / kv_sum over T (deterministic, no atomics). grid (4,32) x 128 thr.
__global__ void k_rkv() {
    int b = blockIdx.y, n = blockIdx.x*128 + threadIdx.x;
    const float* Kp = g_k + (size_t)b*Tn*Dn + n;
    const float* Vp = g_v + (size_t)b*Tn*Dn + n;
    float sk = 0.f, sv = 0.f;
#pragma unroll 8
    for (int t = 0; t < Tn; t++) {
        float kk = Kp[(size_t)t*Dn];
        float vv = Vp[(size_t)t*Dn];
        sk += kk; sv += kk*vv;
    }
    g_ks[b*Dn+n] = sk; g_kvs[b*Dn+n] = sv;
}

// per-token attention combine + gate -> x2 (in place into g_x)
__global__ void k_attn() {
    int bt = blockIdx.x, b = bt >> 11;
    int tid = threadIdx.x, wid = tid >> 5, lane = tid & 31;
    __shared__ float sp[8][4];
    __shared__ float sf[4];
    const float* qr  = g_q + (size_t)bt*Dn;
    const float* ks  = g_ks  + b*Dn;
    const float* kvs = g_kvs + b*Dn;
    float q0 = qr[tid], q1 = qr[tid+256];
    float pn0 = q0*kvs[tid],     pd0 = q0*ks[tid];
    float pn1 = q1*kvs[tid+256], pd1 = q1*ks[tid+256];
#pragma unroll
    for (int o = 16; o; o >>= 1) {
        pn0 += __shfl_xor_sync(~0u,pn0,o); pd0 += __shfl_xor_sync(~0u,pd0,o);
        pn1 += __shfl_xor_sync(~0u,pn1,o); pd1 += __shfl_xor_sync(~0u,pd1,o);
    }
    if (lane == 0) { sp[wid][0]=pn0; sp[wid][1]=pd0; sp[wid][2]=pn1; sp[wid][3]=pd1; }
    __syncthreads();
    if (tid == 0) {
        float a=0,c=0,d=0,e=0;
        for (int w = 0; w < 8; w++) { a+=sp[w][0]; c+=sp[w][1]; d+=sp[w][2]; e+=sp[w][3]; }
        sf[0]=a; sf[1]=c; sf[2]=d; sf[3]=e;
    }
    __syncthreads();
    float s0 = sf[0] / (sf[1] + 1e-6f);
    float s1 = sf[2] / (sf[3] + 1e-6f);
    float* xr = g_x + (size_t)bt*Dn;
    const float* gr = g_g + (size_t)bt*Dn;
    float ga = gr[tid],   xa = xr[tid];
    float gb = gr[tid+256], xb = xr[tid+256];
    xr[tid]     = ga*s0 + (1.f-ga)*xa;
    xr[tid+256] = gb*s1 + (1.f-gb)*xb;
}

// transpose fast_W; exp(log_dt/log_tau)
__global__ void k_prep(const float* __restrict__ fw, const float* __restrict__ ldt,
                       const float* __restrict__ ltau) {
    int i = blockIdx.x*256 + threadIdx.x;      // 0..262143
    int r = i >> 9, c = i & 511;
    g_fT[c*Hn + r] = fw[r*Hn + c];             // fT[j][i] = fw[i][j]
    if (i < Hn) { g_dt[i] = expf(ldt[i]); g_tau[i] = expf(ltau[i]); }
}

// Persistent recurrence: 128 blocks (64 j-chunks x 2 b-halves), 256 thr,
// one software grid barrier per step. Weights for this block's 8 j-rows are
// cached in SMEM once. Lane = (batch 0..15, K-half 0..1).
__global__ __launch_bounds__(256,1) void k_recur(const float* __restrict__ Wh,
                                                 const float* __restrict__ Wz) {
    extern __shared__ float sm[];
    float* ws = sm;                 // [3][8][512] = 12288 floats
    float* hs = sm + 12288;         // [512*17]   =  8704 floats
    int bh = blockIdx.x & 1, jc = blockIdx.x >> 1;
    int tid = threadIdx.x, wid = tid >> 5, lane = tid & 31;
    int j0 = jc * 8;

    // cache weight rows (coalesced float4)
    {
        const float4* s0 = (const float4*)(Wh   + (size_t)j0*Hn);
        const float4* s1 = (const float4*)(Wz   + (size_t)j0*Hn);
        const float4* s2 = (const float4*)(g_fT + (size_t)j0*Hn);
        float4* d0 = (float4*)(ws);
        float4* d1 = (float4*)(ws + 4096);
        float4* d2 = (float4*)(ws + 8192);
        for (int q = tid; q < 1024; q += 256) { d0[q]=s0[q]; d1[q]=s1[q]; d2[q]=s2[q]; }
    }
    int j = j0 + wid;
    float dtj = g_dt[j], tauj = g_tau[j];
    int b = lane >> 1, ih = lane & 1, ib = ih*256;
    int bg = bh*16 + b;
    const float4* WH = (const float4*)(ws +        wid*512 + ib);
    const float4* WZ = (const float4*)(ws + 4096 + wid*512 + ib);
    const float4* WF = (const float4*)(ws + 8192 + wid*512 + ib);
    const float* xin = g_q + (size_t)bg*Tn*Hn + j;
    const float* xzx = g_k + (size_t)bg*Tn*Hn + j;

    for (int t = 0; t < Tn; t++) {
        // stage h for this block's 16 batches: hs[i*17+b]
        const float4* hp = (const float4*)(g_h[t & 1] + (size_t)bh*16*Hn);
        for (int q = tid; q < 2048; q += 256) {
            float4 hv = __ldcg(hp + q);
            int bb = q >> 7;
            int i  = (q*4) & 511;
            hs[(i+0)*17+bb]=hv.x; hs[(i+1)*17+bb]=hv.y;
            hs[(i+2)*17+bb]=hv.z; hs[(i+3)*17+bb]=hv.w;
        }
        __syncthreads();

        float au=0.f, az=0.f, af=0.f;
#pragma unroll 8
        for (int q4 = 0; q4 < 64; q4++) {
            float4 a = WH[q4], c = WZ[q4], e = WF[q4];
            int i0 = (ib + q4*4)*17 + b;
            float h0=hs[i0], h1=hs[i0+17], h2=hs[i0+34], h3=hs[i0+51];
            au += a.x*h0 + a.y*h1 + a.z*h2 + a.w*h3;
            az += c.x*h0 + c.y*h1 + c.z*h2 + c.w*h3;
            af += e.x*h0 + e.y*h1 + e.z*h2 + e.w*h3;
        }
        au += __shfl_xor_sync(~0u, au, 1);
        az += __shfl_xor_sync(~0u, az, 1);
        af += __shfl_xor_sync(~0u, af, 1);
        if (ih == 0) {
            float h  = hs[j*17 + b];
            float u  = xin[(size_t)t*Hn] + au;
            float f  = tanhf(u);
            float hl = h + dtj*(f - tauj*h);
            float z  = 1.f/(1.f+__expf(-(xzx[(size_t)t*Hn] + az)));
            float hn2 = (1.f - z)*h + z*hl + af;
            __stcg(&g_h[(t & 1) ^ 1][(size_t)bg*Hn + j], hn2);
        }
        // grid barrier (release: fence before arrive; acquire: fence after spin)
        __syncthreads();
        if (tid == 0) {
            __threadfence();
            atomicAdd(&g_barrier, 1u);
            unsigned target = 128u * (unsigned)(t + 1);
            while (*((volatile unsigned*)&g_barrier) < target) { }
            __threadfence();
        }
        __syncthreads();
    }
}

// pred_error_norm = sqrt(mean((h_last - h_prev)^2)); h_last=g_h[0], h_prev=g_h[1]
__global__ void k_pe(float* out) {
    __shared__ float sr[512];
    float s = 0.f;
    for (int i = threadIdx.x; i < Bn*Hn; i += 512) {
        float d = g_h[0][i] - g_h[1][i]; s += d*d;
    }
    sr[threadIdx.x] = s; __syncthreads();
    for (int o = 256; o; o >>= 1) {
        if (threadIdx.x < o) sr[threadIdx.x] += sr[threadIdx.x + o];
        __syncthreads();
    }
    if (threadIdx.x == 0)
        out[(size_t)Bn*Vn + (size_t)Bn*Hn] = sqrtf(sr[0] / (float)(Bn*Hn));
}

// LayerNorm of h_last -> g_hn and out[B*V ..]
__global__ void k_ln(const float* __restrict__ lng, const float* __restrict__ lnb,
                     float* out) {
    int b = blockIdx.x, j = threadIdx.x;
    __shared__ float sr[512];
    __shared__ float stat;
    float hv = g_h[0][b*Hn + j];
    sr[j] = hv; __syncthreads();
    for (int o = 256; o; o >>= 1) { if (j < o) sr[j] += sr[j+o]; __syncthreads(); }
    if (j == 0) stat = sr[0] / (float)Hn;
    __syncthreads();
    float mu = stat, d = hv - mu;
    __syncthreads();
    sr[j] = d*d; __syncthreads();
    for (int o = 256; o; o >>= 1) { if (j < o) sr[j] += sr[j+o]; __syncthreads(); }
    if (j == 0) stat = rsqrtf(sr[0] / (float)Hn + 1e-5f);
    __syncthreads();
    float y = d * stat * lng[j] + lnb[j];
    g_hn[b*Hn + j] = y;
    out[(size_t)Bn*Vn + b*Hn + j] = y;
}

// logits = g_hn @ Wlm^T + blm. grid (786, 2 bhalf) x 256 thr.
__global__ void k_logits(const float* __restrict__ Wlm, const float* __restrict__ blm,
                         float* out) {
    __shared__ float hs[16*516];
    int bh = blockIdx.y, tid = threadIdx.x, wid = tid >> 5, lane = tid & 31;
    int b = lane & 15, vh = lane >> 4;
#pragma unroll
    for (int m = 0; m < 32; m++) {
        int idx = tid + m*256;
        int bb = idx >> 9, k = idx & 511;
        hs[bb*516 + k] = g_hn[(bh*16 + bb)*Hn + k];
    }
    __syncthreads();
    const float4* H4 = (const float4*)(hs + b*516);
#pragma unroll
    for (int s = 0; s < 4; s++) {
        int v = blockIdx.x*64 + wid*8 + s*2 + vh;
        if (v < Vn) {
            const float4* W4 = (const float4*)(Wlm + (size_t)v*Hn);
            float acc = 0.f;
#pragma unroll 8
            for (int k4 = 0; k4 < 128; k4++) {
                float4 w = W4[k4], h = H4[k4];
                acc += w.x*h.x + w.y*h.y + w.z*h.z + w.w*h.w;
            }
            out[(size_t)(bh*16 + b)*Vn + v] = acc + blm[v];
        }
    }
}

extern "C" void kernel_launch(void* const* d_in, const int* in_sizes, int n_in,
                              void* d_out, int out_size) {
    const int*   ids  = (const int*)  d_in[0];
    const float* emb  = (const float*)d_in[1];
    const float* Wq   = (const float*)d_in[2];
    const float* Wk   = (const float*)d_in[3];
    const float* Wv   = (const float*)d_in[4];
    // d_in[5] = Wo (unused by forward)
    const float* Wg   = (const float*)d_in[6];
    const float* bg   = (const float*)d_in[7];
    const float* Win  = (const float*)d_in[8];
    const float* bin  = (const float*)d_in[9];
    const float* Wh   = (const float*)d_in[10];
    const float* ltau = (const float*)d_in[11];
    const float* ldt  = (const float*)d_in[12];
    const float* Wzx  = (const float*)d_in[13];
    const float* bzx  = (const float*)d_in[14];
    const float* Wzh  = (const float*)d_in[15];
    const float* fw   = (const float*)d_in[16];
    const float* lng  = (const float*)d_in[17];
    const float* lnb  = (const float*)d_in[18];
    const float* Wlm  = (const float*)d_in[19];
    const float* blm  = (const float*)d_in[20];
    float* out = (float*)d_out;

    static int smem_set = 0;
    const int recur_smem = (12288 + 512*17) * 4;   // 83,968 bytes
    if (!smem_set) {
        cudaFuncSetAttribute(k_recur, cudaFuncAttributeMaxDynamicSharedMemorySize,
                             recur_smem);
        smem_set = 1;
    }

    k_init<<<64, 256>>>();
    k_embed<<<BTn, 128>>>(ids, emb);

    dim3 gp(BTn/128, 4);
    k_proj<<<gp, 256>>>(0, Wq, nullptr, 1);   // q = phi(x Wq^T)
    k_proj<<<gp, 256>>>(1, Wk, nullptr, 1);   // k = phi(x Wk^T)
    k_proj<<<gp, 256>>>(2, Wv, nullptr, 0);   // v
    k_proj<<<gp, 256>>>(3, Wg, bg,      2);   // gate = sigmoid(x Wg^T + bg)

    k_rkv<<<dim3(4, 32), 128>>>();
    k_attn<<<BTn, 256>>>();                   // x2 -> g_x (in place)

    k_proj<<<gp, 256>>>(0, Win, bin, 0);      // xin -> g_q
    k_proj<<<gp, 256>>>(1, Wzx, bzx, 0);      // xzx -> g_k
    k_prep<<<1024, 256>>>(fw, ldt, ltau);

    k_recur<<<128, 256, recur_smem>>>(Wh, Wzh);

    k_ln<<<32, 512>>>(lng, lnb, out);
    k_pe<<<1, 512>>>(out);
    k_logits<<<dim3(786, 2), 256>>>(Wlm, blm, out);
}

// round 9
// speedup vs baseline: 1.4381x; 1.4381x over previous
#include <cuda_runtime.h>
#include <math.h>

#define Bn 32
#define Tn 2048
#define Vn 50257
#define Dn 512
#define Hn 512
#define BTn (Bn*Tn)

// ------- scratch (__device__ globals: allocation-free) -------
__device__ float g_x[(size_t)BTn*Dn];   // x, then x2 in place
__device__ float g_q[(size_t)BTn*Dn];   // q, then xin
__device__ float g_k[(size_t)BTn*Dn];   // k, then xzx
__device__ float g_v[(size_t)BTn*Dn];
__device__ float g_g[(size_t)BTn*Dn];
__device__ float g_ks[Bn*Dn];
__device__ float g_kvs[Bn*Dn];
__device__ float g_h[2][Bn*Hn];
__device__ float g_hn[Bn*Hn];
__device__ float g_fT[Hn*Hn];
__device__ float g_dt[Hn];
__device__ float g_tau[Hn];
__device__ unsigned g_barrier[2];

__global__ void k_init() {
    int i = blockIdx.x * 256 + threadIdx.x;
    if (i < Bn*Hn) { g_h[0][i] = 0.f; g_ks[i] = 0.f; g_kvs[i] = 0.f; }
    if (i < 2) g_barrier[i] = 0u;
}

__global__ void k_embed(const int* __restrict__ ids, const float* __restrict__ emb) {
    int bt = blockIdx.x;
    int id = ids[bt];
    ((float4*)(g_x + (size_t)bt * Dn))[threadIdx.x] =
        ((const float4*)(emb + (size_t)id * Dn))[threadIdx.x];
}

// C[m,n] = act( sum_k X[m,k]*W[n,k] + bias[n] ), X = g_x always.
// 128x128 tile, K-tile 8, 256 thr, 8x8/thread. osel: 0 q,1 k,2 v,3 g.
__global__ __launch_bounds__(256,2) void k_proj(int osel, const float* __restrict__ W,
                                                const float* __restrict__ bias, int act) {
    float* outp = (osel==0)?g_q:(osel==1)?g_k:(osel==2)?g_v:g_g;
    __shared__ float As[8][132];
    __shared__ float Bs[8][132];
    int tid = threadIdx.x;
    int tx = tid & 15, ty = tid >> 4;
    int m0 = blockIdx.x * 128, n0 = blockIdx.y * 128;
    int lrow = tid >> 1, lcol = (tid & 1) * 4;
    const float* Ap = g_x + (size_t)(m0 + lrow) * Dn + lcol;
    const float* Bp = W   + (size_t)(n0 + lrow) * Dn + lcol;
    float acc[8][8];
#pragma unroll
    for (int i = 0; i < 8; i++)
#pragma unroll
        for (int j = 0; j < 8; j++) acc[i][j] = 0.f;
    for (int kt = 0; kt < 64; kt++) {
        float4 av = *(const float4*)(Ap + kt*8);
        float4 bv = *(const float4*)(Bp + kt*8);
        __syncthreads();
        As[lcol+0][lrow]=av.x; As[lcol+1][lrow]=av.y; As[lcol+2][lrow]=av.z; As[lcol+3][lrow]=av.w;
        Bs[lcol+0][lrow]=bv.x; Bs[lcol+1][lrow]=bv.y; Bs[lcol+2][lrow]=bv.z; Bs[lcol+3][lrow]=bv.w;
        __syncthreads();
#pragma unroll
        for (int kk = 0; kk < 8; kk++) {
            float a[8], b[8];
            *(float4*)(a)   = *(const float4*)&As[kk][ty*8];
            *(float4*)(a+4) = *(const float4*)&As[kk][ty*8+4];
            *(float4*)(b)   = *(const float4*)&Bs[kk][tx*8];
            *(float4*)(b+4) = *(const float4*)&Bs[kk][tx*8+4];
#pragma unroll
            for (int i = 0; i < 8; i++)
#pragma unroll
                for (int j = 0; j < 8; j++) acc[i][j] += a[i]*b[j];
        }
    }
#pragma unroll
    for (int i = 0; i < 8; i++) {
        int m = m0 + ty*8 + i;
#pragma unroll
        for (int j = 0; j < 8; j++) {
            int n = n0 + tx*8 + j;
            float c = acc[i][j];
            if (bias) c += bias[n];
            if (act == 1)      c = (c > 0.f) ? (c + 1.f) : __expf(c);  // elu+1
            else if (act == 2) c = 1.f / (1.f + __expf(-c));           // sigmoid
            outp[(size_t)m * Dn + n] = c;
        }
    }
}

// k_sum / kv_sum over T (deterministic, no atomics). grid (4,32) x 128 thr.
__global__ void k_rkv() {
    int b = blockIdx.y, n = blockIdx.x*128 + threadIdx.x;
    const float* Kp = g_k + (size_t)b*Tn*Dn + n;
    const float* Vp = g_v + (size_t)b*Tn*Dn + n;
    float sk = 0.f, sv = 0.f;
#pragma unroll 8
    for (int t = 0; t < Tn; t++) {
        float kk = Kp[(size_t)t*Dn];
        float vv = Vp[(size_t)t*Dn];
        sk += kk; sv += kk*vv;
    }
    g_ks[b*Dn+n] = sk; g_kvs[b*Dn+n] = sv;
}

// per-token attention combine + gate -> x2 (in place into g_x)
__global__ void k_attn() {
    int bt = blockIdx.x, b = bt >> 11;
    int tid = threadIdx.x, wid = tid >> 5, lane = tid & 31;
    __shared__ float sp[8][4];
    __shared__ float sf[4];
    const float* qr  = g_q + (size_t)bt*Dn;
    const float* ks  = g_ks  + b*Dn;
    const float* kvs = g_kvs + b*Dn;
    float q0 = qr[tid], q1 = qr[tid+256];
    float pn0 = q0*kvs[tid],     pd0 = q0*ks[tid];
    float pn1 = q1*kvs[tid+256], pd1 = q1*ks[tid+256];
#pragma unroll
    for (int o = 16; o; o >>= 1) {
        pn0 += __shfl_xor_sync(~0u,pn0,o); pd0 += __shfl_xor_sync(~0u,pd0,o);
        pn1 += __shfl_xor_sync(~0u,pn1,o); pd1 += __shfl_xor_sync(~0u,pd1,o);
    }
    if (lane == 0) { sp[wid][0]=pn0; sp[wid][1]=pd0; sp[wid][2]=pn1; sp[wid][3]=pd1; }
    __syncthreads();
    if (tid == 0) {
        float a=0,c=0,d=0,e=0;
        for (int w = 0; w < 8; w++) { a+=sp[w][0]; c+=sp[w][1]; d+=sp[w][2]; e+=sp[w][3]; }
        sf[0]=a; sf[1]=c; sf[2]=d; sf[3]=e;
    }
    __syncthreads();
    float s0 = sf[0] / (sf[1] + 1e-6f);
    float s1 = sf[2] / (sf[3] + 1e-6f);
    float* xr = g_x + (size_t)bt*Dn;
    const float* gr = g_g + (size_t)bt*Dn;
    float ga = gr[tid],   xa = xr[tid];
    float gb = gr[tid+256], xb = xr[tid+256];
    xr[tid]     = ga*s0 + (1.f-ga)*xa;
    xr[tid+256] = gb*s1 + (1.f-gb)*xb;
}

// transpose fast_W; exp(log_dt/log_tau)
__global__ void k_prep(const float* __restrict__ fw, const float* __restrict__ ldt,
                       const float* __restrict__ ltau) {
    int i = blockIdx.x*256 + threadIdx.x;      // 0..262143
    int r = i >> 9, c = i & 511;
    g_fT[c*Hn + r] = fw[r*Hn + c];             // fT[j][i] = fw[i][j]
    if (i < Hn) { g_dt[i] = expf(ldt[i]); g_tau[i] = expf(ltau[i]); }
}

// Persistent recurrence: 128 blocks = 64 j-chunks x 2 batch-halves, 256 thr.
// The two batch-halves are fully independent -> separate 64-block barriers.
// h staged as hs[b*516 + i] (conflict-free LDS.128/STS.128); lane = ih*16 + b.
__global__ __launch_bounds__(256,1) void k_recur(const float* __restrict__ Wh,
                                                 const float* __restrict__ Wz) {
    extern __shared__ float sm[];
    float* ws = sm;                 // [3][8][512] = 12288 floats (48KB)
    float* hs = sm + 12288;         // [16][516]  =  8256 floats (33KB)
    int bh = blockIdx.x & 1, jc = blockIdx.x >> 1;
    int tid = threadIdx.x, wid = tid >> 5, lane = tid & 31;
    int j0 = jc * 8;

    // cache this block's 8 weight rows of each matrix (coalesced float4)
    {
        const float4* s0 = (const float4*)(Wh   + (size_t)j0*Hn);
        const float4* s1 = (const float4*)(Wz   + (size_t)j0*Hn);
        const float4* s2 = (const float4*)(g_fT + (size_t)j0*Hn);
        float4* d0 = (float4*)(ws);
        float4* d1 = (float4*)(ws + 4096);
        float4* d2 = (float4*)(ws + 8192);
        for (int q = tid; q < 1024; q += 256) { d0[q]=s0[q]; d1[q]=s1[q]; d2[q]=s2[q]; }
    }
    int j = j0 + wid;
    float dtj = g_dt[j], tauj = g_tau[j];
    int b = lane & 15, ih = lane >> 4, ib = ih*256;
    int bg = bh*16 + b;
    const float4* WH = (const float4*)(ws +        wid*512 + ib);
    const float4* WZ = (const float4*)(ws + 4096 + wid*512 + ib);
    const float4* WF = (const float4*)(ws + 8192 + wid*512 + ib);
    const float* xin = g_q + (size_t)bg*Tn*Hn + j;
    const float* xzx = g_k + (size_t)bg*Tn*Hn + j;
    unsigned* bar = &g_barrier[bh];

    for (int t = 0; t < Tn; t++) {
        // prefetch the per-step inputs (hide DRAM latency under the dot loop)
        float xi = xin[(size_t)t*Hn];
        float xz = xzx[(size_t)t*Hn];

        // stage h: coalesced LDG.128 -> conflict-free STS.128
        const float4* hp = (const float4*)(g_h[t & 1] + (size_t)bh*16*Hn);
#pragma unroll
        for (int m = 0; m < 8; m++) {
            int idx = tid + m*256;          // 0..2047 = bb(4b) * 128 + c
            int bb = idx >> 7, c = idx & 127;
            float4 hv = __ldcg(hp + idx);
            *(float4*)(hs + bb*516 + c*4) = hv;
        }
        __syncthreads();

        const float* hb = hs + b*516 + ib;
        float au=0.f, az=0.f, af=0.f;
#pragma unroll 8
        for (int q4 = 0; q4 < 64; q4++) {
            float4 a  = WH[q4];
            float4 c4 = WZ[q4];
            float4 e  = WF[q4];
            float4 h4 = *(const float4*)(hb + q4*4);
            au += a.x*h4.x + a.y*h4.y + a.z*h4.z + a.w*h4.w;
            az += c4.x*h4.x + c4.y*h4.y + c4.z*h4.z + c4.w*h4.w;
            af += e.x*h4.x + e.y*h4.y + e.z*h4.z + e.w*h4.w;
        }
        au += __shfl_xor_sync(~0u, au, 16);
        az += __shfl_xor_sync(~0u, az, 16);
        af += __shfl_xor_sync(~0u, af, 16);
        if (ih == 0) {
            float h  = hs[b*516 + j];
            float u  = xi + au;
            float f  = tanhf(u);
            float hl = h + dtj*(f - tauj*h);
            float z  = 1.f/(1.f+__expf(-(xz + az)));
            float hn2 = (1.f - z)*h + z*hl + af;
            __stcg(&g_h[(t & 1) ^ 1][(size_t)bg*Hn + j], hn2);
        }
        // 64-block grid barrier for this batch-half (release/acquire)
        __syncthreads();
        if (tid == 0) {
            __threadfence();
            atomicAdd(bar, 1u);
            unsigned target = 64u * (unsigned)(t + 1);
            while (*((volatile unsigned*)bar) < target) { }
            __threadfence();
        }
        __syncthreads();
    }
}

// pred_error_norm = sqrt(mean((h_last - h_prev)^2)); h_last=g_h[0], h_prev=g_h[1]
__global__ void k_pe(float* out) {
    __shared__ float sr[512];
    float s = 0.f;
    for (int i = threadIdx.x; i < Bn*Hn; i += 512) {
        float d = g_h[0][i] - g_h[1][i]; s += d*d;
    }
    sr[threadIdx.x] = s; __syncthreads();
    for (int o = 256; o; o >>= 1) {
        if (threadIdx.x < o) sr[threadIdx.x] += sr[threadIdx.x + o];
        __syncthreads();
    }
    if (threadIdx.x == 0)
        out[(size_t)Bn*Vn + (size_t)Bn*Hn] = sqrtf(sr[0] / (float)(Bn*Hn));
}

// LayerNorm of h_last -> g_hn and out[B*V ..]
__global__ void k_ln(const float* __restrict__ lng, const float* __restrict__ lnb,
                     float* out) {
    int b = blockIdx.x, j = threadIdx.x;
    __shared__ float sr[512];
    __shared__ float stat;
    float hv = g_h[0][b*Hn + j];
    sr[j] = hv; __syncthreads();
    for (int o = 256; o; o >>= 1) { if (j < o) sr[j] += sr[j+o]; __syncthreads(); }
    if (j == 0) stat = sr[0] / (float)Hn;
    __syncthreads();
    float mu = stat, d = hv - mu;
    __syncthreads();
    sr[j] = d*d; __syncthreads();
    for (int o = 256; o; o >>= 1) { if (j < o) sr[j] += sr[j+o]; __syncthreads(); }
    if (j == 0) stat = rsqrtf(sr[0] / (float)Hn + 1e-5f);
    __syncthreads();
    float y = d * stat * lng[j] + lnb[j];
    g_hn[b*Hn + j] = y;
    out[(size_t)Bn*Vn + b*Hn + j] = y;
}

// logits = g_hn @ Wlm^T + blm. grid (786, 2 bhalf) x 256 thr.
__global__ void k_logits(const float* __restrict__ Wlm, const float* __restrict__ blm,
                         float* out) {
    __shared__ float hs[16*516];
    int bh = blockIdx.y, tid = threadIdx.x, wid = tid >> 5, lane = tid & 31;
    int b = lane & 15, vh = lane >> 4;
#pragma unroll
    for (int m = 0; m < 32; m++) {
        int idx = tid + m*256;
        int bb = idx >> 9, k = idx & 511;
        hs[bb*516 + k] = g_hn[(bh*16 + bb)*Hn + k];
    }
    __syncthreads();
    const float4* H4 = (const float4*)(hs + b*516);
#pragma unroll
    for (int s = 0; s < 4; s++) {
        int v = blockIdx.x*64 + wid*8 + s*2 + vh;
        if (v < Vn) {
            const float4* W4 = (const float4*)(Wlm + (size_t)v*Hn);
            float acc = 0.f;
#pragma unroll 8
            for (int k4 = 0; k4 < 128; k4++) {
                float4 w = W4[k4], h = H4[k4];
                acc += w.x*h.x + w.y*h.y + w.z*h.z + w.w*h.w;
            }
            out[(size_t)(bh*16 + b)*Vn + v] = acc + blm[v];
        }
    }
}

extern "C" void kernel_launch(void* const* d_in, const int* in_sizes, int n_in,
                              void* d_out, int out_size) {
    const int*   ids  = (const int*)  d_in[0];
    const float* emb  = (const float*)d_in[1];
    const float* Wq   = (const float*)d_in[2];
    const float* Wk   = (const float*)d_in[3];
    const float* Wv   = (const float*)d_in[4];
    // d_in[5] = Wo (unused by forward)
    const float* Wg   = (const float*)d_in[6];
    const float* bg   = (const float*)d_in[7];
    const float* Win  = (const float*)d_in[8];
    const float* bin  = (const float*)d_in[9];
    const float* Wh   = (const float*)d_in[10];
    const float* ltau = (const float*)d_in[11];
    const float* ldt  = (const float*)d_in[12];
    const float* Wzx  = (const float*)d_in[13];
    const float* bzx  = (const float*)d_in[14];
    const float* Wzh  = (const float*)d_in[15];
    const float* fw   = (const float*)d_in[16];
    const float* lng  = (const float*)d_in[17];
    const float* lnb  = (const float*)d_in[18];
    const float* Wlm  = (const float*)d_in[19];
    const float* blm  = (const float*)d_in[20];
    float* out = (float*)d_out;

    static int smem_set = 0;
    const int recur_smem = (12288 + 16*516) * 4;   // 82,176 bytes
    if (!smem_set) {
        cudaFuncSetAttribute(k_recur, cudaFuncAttributeMaxDynamicSharedMemorySize,
                             recur_smem);
        smem_set = 1;
    }

    k_init<<<64, 256>>>();
    k_embed<<<BTn, 128>>>(ids, emb);

    dim3 gp(BTn/128, 4);
    k_proj<<<gp, 256>>>(0, Wq, nullptr, 1);   // q = phi(x Wq^T)
    k_proj<<<gp, 256>>>(1, Wk, nullptr, 1);   // k = phi(x Wk^T)
    k_proj<<<gp, 256>>>(2, Wv, nullptr, 0);   // v
    k_proj<<<gp, 256>>>(3, Wg, bg,      2);   // gate = sigmoid(x Wg^T + bg)

    k_rkv<<<dim3(4, 32), 128>>>();
    k_attn<<<BTn, 256>>>();                   // x2 -> g_x (in place)

    k_proj<<<gp, 256>>>(0, Win, bin, 0);      // xin -> g_q
    k_proj<<<gp, 256>>>(1, Wzx, bzx, 0);      // xzx -> g_k
    k_prep<<<1024, 256>>>(fw, ldt, ltau);

    k_recur<<<128, 256, recur_smem>>>(Wh, Wzh);

    k_ln<<<32, 512>>>(lng, lnb, out);
    k_pe<<<1, 512>>>(out);
    k_logits<<<dim3(786, 2), 256>>>(Wlm, blm, out);
}

// round 10
// speedup vs baseline: 1.5441x; 1.0737x over previous
#include <cuda_runtime.h>
#include <math.h>

#define Bn 32
#define Tn 2048
#define Vn 50257
#define Dn 512
#define Hn 512
#define BTn (Bn*Tn)

// ------- scratch (__device__ globals: allocation-free) -------
__device__ float g_x[(size_t)BTn*Dn];   // x, then x2 in place
__device__ float g_q[(size_t)BTn*Dn];   // q, then xin
__device__ float g_k[(size_t)BTn*Dn];   // k, then xzx
__device__ float g_v[(size_t)BTn*Dn];
__device__ float g_g[(size_t)BTn*Dn];
__device__ float g_ks[Bn*Dn];
__device__ float g_kvs[Bn*Dn];
__device__ float g_h[2][Bn*Hn];
__device__ float g_hn[Bn*Hn];
__device__ float g_fT[Hn*Hn];
__device__ float g_dt[Hn];
__device__ float g_tau[Hn];
__device__ unsigned g_barrier[2];
__device__ unsigned g_fw_nz;

__global__ void k_init() {
    int i = blockIdx.x * 256 + threadIdx.x;
    if (i < Bn*Hn) { g_h[0][i] = 0.f; g_ks[i] = 0.f; g_kvs[i] = 0.f; }
    if (i < 2) g_barrier[i] = 0u;
    if (i == 2) g_fw_nz = 0u;
}

__global__ void k_embed(const int* __restrict__ ids, const float* __restrict__ emb) {
    int bt = blockIdx.x;
    int id = ids[bt];
    ((float4*)(g_x + (size_t)bt * Dn))[threadIdx.x] =
        ((const float4*)(emb + (size_t)id * Dn))[threadIdx.x];
}

// C[m,n] = act( sum_k X[m,k]*W[n,k] + bias[n] ), X = g_x always.
// 128x128 tile, K-tile 8, 256 thr, 8x8/thread. osel: 0 q,1 k,2 v,3 g.
__global__ __launch_bounds__(256,2) void k_proj(int osel, const float* __restrict__ W,
                                                const float* __restrict__ bias, int act) {
    float* outp = (osel==0)?g_q:(osel==1)?g_k:(osel==2)?g_v:g_g;
    __shared__ float As[8][132];
    __shared__ float Bs[8][132];
    int tid = threadIdx.x;
    int tx = tid & 15, ty = tid >> 4;
    int m0 = blockIdx.x * 128, n0 = blockIdx.y * 128;
    int lrow = tid >> 1, lcol = (tid & 1) * 4;
    const float* Ap = g_x + (size_t)(m0 + lrow) * Dn + lcol;
    const float* Bp = W   + (size_t)(n0 + lrow) * Dn + lcol;
    float acc[8][8];
#pragma unroll
    for (int i = 0; i < 8; i++)
#pragma unroll
        for (int j = 0; j < 8; j++) acc[i][j] = 0.f;
    for (int kt = 0; kt < 64; kt++) {
        float4 av = *(const float4*)(Ap + kt*8);
        float4 bv = *(const float4*)(Bp + kt*8);
        __syncthreads();
        As[lcol+0][lrow]=av.x; As[lcol+1][lrow]=av.y; As[lcol+2][lrow]=av.z; As[lcol+3][lrow]=av.w;
        Bs[lcol+0][lrow]=bv.x; Bs[lcol+1][lrow]=bv.y; Bs[lcol+2][lrow]=bv.z; Bs[lcol+3][lrow]=bv.w;
        __syncthreads();
#pragma unroll
        for (int kk = 0; kk < 8; kk++) {
            float a[8], b[8];
            *(float4*)(a)   = *(const float4*)&As[kk][ty*8];
            *(float4*)(a+4) = *(const float4*)&As[kk][ty*8+4];
            *(float4*)(b)   = *(const float4*)&Bs[kk][tx*8];
            *(float4*)(b+4) = *(const float4*)&Bs[kk][tx*8+4];
#pragma unroll
            for (int i = 0; i < 8; i++)
#pragma unroll
                for (int j = 0; j < 8; j++) acc[i][j] += a[i]*b[j];
        }
    }
#pragma unroll
    for (int i = 0; i < 8; i++) {
        int m = m0 + ty*8 + i;
#pragma unroll
        for (int j = 0; j < 8; j++) {
            int n = n0 + tx*8 + j;
            float c = acc[i][j];
            if (bias) c += bias[n];
            if (act == 1)      c = (c > 0.f) ? (c + 1.f) : __expf(c);  // elu+1
            else if (act == 2) c = 1.f / (1.f + __expf(-c));           // sigmoid
            outp[(size_t)m * Dn + n] = c;
        }
    }
}

// k_sum / kv_sum over T (deterministic, no atomics). grid (4,32) x 128 thr.
__global__ void k_rkv() {
    int b = blockIdx.y, n = blockIdx.x*128 + threadIdx.x;
    const float* Kp = g_k + (size_t)b*Tn*Dn + n;
    const float* Vp = g_v + (size_t)b*Tn*Dn + n;
    float sk = 0.f, sv = 0.f;
#pragma unroll 8
    for (int t = 0; t < Tn; t++) {
        float kk = Kp[(size_t)t*Dn];
        float vv = Vp[(size_t)t*Dn];
        sk += kk; sv += kk*vv;
    }
    g_ks[b*Dn+n] = sk; g_kvs[b*Dn+n] = sv;
}

// per-token attention combine + gate -> x2 (in place into g_x)
__global__ void k_attn() {
    int bt = blockIdx.x, b = bt >> 11;
    int tid = threadIdx.x, wid = tid >> 5, lane = tid & 31;
    __shared__ float sp[8][4];
    __shared__ float sf[4];
    const float* qr  = g_q + (size_t)bt*Dn;
    const float* ks  = g_ks  + b*Dn;
    const float* kvs = g_kvs + b*Dn;
    float q0 = qr[tid], q1 = qr[tid+256];
    float pn0 = q0*kvs[tid],     pd0 = q0*ks[tid];
    float pn1 = q1*kvs[tid+256], pd1 = q1*ks[tid+256];
#pragma unroll
    for (int o = 16; o; o >>= 1) {
        pn0 += __shfl_xor_sync(~0u,pn0,o); pd0 += __shfl_xor_sync(~0u,pd0,o);
        pn1 += __shfl_xor_sync(~0u,pn1,o); pd1 += __shfl_xor_sync(~0u,pd1,o);
    }
    if (lane == 0) { sp[wid][0]=pn0; sp[wid][1]=pd0; sp[wid][2]=pn1; sp[wid][3]=pd1; }
    __syncthreads();
    if (tid == 0) {
        float a=0,c=0,d=0,e=0;
        for (int w = 0; w < 8; w++) { a+=sp[w][0]; c+=sp[w][1]; d+=sp[w][2]; e+=sp[w][3]; }
        sf[0]=a; sf[1]=c; sf[2]=d; sf[3]=e;
    }
    __syncthreads();
    float s0 = sf[0] / (sf[1] + 1e-6f);
    float s1 = sf[2] / (sf[3] + 1e-6f);
    float* xr = g_x + (size_t)bt*Dn;
    const float* gr = g_g + (size_t)bt*Dn;
    float ga = gr[tid],   xa = xr[tid];
    float gb = gr[tid+256], xb = xr[tid+256];
    xr[tid]     = ga*s0 + (1.f-ga)*xa;
    xr[tid+256] = gb*s1 + (1.f-gb)*xb;
}

// transpose fast_W (flag nonzero-ness); exp(log_dt/log_tau)
__global__ void k_prep(const float* __restrict__ fw, const float* __restrict__ ldt,
                       const float* __restrict__ ltau) {
    int i = blockIdx.x*256 + threadIdx.x;      // 0..262143
    int r = i >> 9, c = i & 511;
    float v = fw[i];
    g_fT[c*Hn + r] = v;                        // fT[j][i] = fw[i][j]
    if (v != 0.f) atomicOr(&g_fw_nz, 1u);
    if (i < Hn) { g_dt[i] = expf(ldt[i]); g_tau[i] = expf(ltau[i]); }
}

// Persistent recurrence: 128 blocks = 64 j-chunks x 2 batch-halves, 256 thr.
// Separate 64-block barrier per batch-half. h staged as hs[b*516+i]
// (conflict-free LDS.128/STS.128); lane = ih*16 + b. fast_W matvec skipped
// when the matrix is all-zero (runtime flag, deterministic).
__global__ __launch_bounds__(256,1) void k_recur(const float* __restrict__ Wh,
                                                 const float* __restrict__ Wz) {
    extern __shared__ float sm[];
    float* ws = sm;                 // [3][8][512] = 12288 floats (48KB)
    float* hs = sm + 12288;         // [16][516]  =  8256 floats (33KB)
    int bh = blockIdx.x & 1, jc = blockIdx.x >> 1;
    int tid = threadIdx.x, wid = tid >> 5, lane = tid & 31;
    int j0 = jc * 8;
    unsigned use_f = g_fw_nz;

    // cache this block's 8 weight rows of each matrix (coalesced float4)
    {
        const float4* s0 = (const float4*)(Wh   + (size_t)j0*Hn);
        const float4* s1 = (const float4*)(Wz   + (size_t)j0*Hn);
        float4* d0 = (float4*)(ws);
        float4* d1 = (float4*)(ws + 4096);
        for (int q = tid; q < 1024; q += 256) { d0[q]=s0[q]; d1[q]=s1[q]; }
        if (use_f) {
            const float4* s2 = (const float4*)(g_fT + (size_t)j0*Hn);
            float4* d2 = (float4*)(ws + 8192);
            for (int q = tid; q < 1024; q += 256) d2[q]=s2[q];
        }
    }
    int j = j0 + wid;
    float dtj = g_dt[j], tauj = g_tau[j];
    int b = lane & 15, ih = lane >> 4, ib = ih*256;
    int bg = bh*16 + b;
    const float4* WH = (const float4*)(ws +        wid*512 + ib);
    const float4* WZ = (const float4*)(ws + 4096 + wid*512 + ib);
    const float4* WF = (const float4*)(ws + 8192 + wid*512 + ib);
    const float* xin = g_q + (size_t)bg*Tn*Hn + j;
    const float* xzx = g_k + (size_t)bg*Tn*Hn + j;
    unsigned* bar = &g_barrier[bh];

    float xi = xin[0];
    float xz = xzx[0];

    for (int t = 0; t < Tn; t++) {
        // stage h: coalesced LDG.128 -> conflict-free STS.128
        const float4* hp = (const float4*)(g_h[t & 1] + (size_t)bh*16*Hn);
#pragma unroll
        for (int m = 0; m < 8; m++) {
            int idx = tid + m*256;          // 0..2047 = bb(4b) * 128 + c
            int bb = idx >> 7, c = idx & 127;
            float4 hv = __ldcg(hp + idx);
            *(float4*)(hs + bb*516 + c*4) = hv;
        }
        __syncthreads();

        const float* hb = hs + b*516 + ib;
        float au=0.f, az=0.f, af=0.f;
        if (use_f) {
#pragma unroll 8
            for (int q4 = 0; q4 < 64; q4++) {
                float4 a  = WH[q4];
                float4 c4 = WZ[q4];
                float4 e  = WF[q4];
                float4 h4 = *(const float4*)(hb + q4*4);
                au += a.x*h4.x + a.y*h4.y + a.z*h4.z + a.w*h4.w;
                az += c4.x*h4.x + c4.y*h4.y + c4.z*h4.z + c4.w*h4.w;
                af += e.x*h4.x + e.y*h4.y + e.z*h4.z + e.w*h4.w;
            }
        } else {
#pragma unroll 8
            for (int q4 = 0; q4 < 64; q4++) {
                float4 a  = WH[q4];
                float4 c4 = WZ[q4];
                float4 h4 = *(const float4*)(hb + q4*4);
                au += a.x*h4.x + a.y*h4.y + a.z*h4.z + a.w*h4.w;
                az += c4.x*h4.x + c4.y*h4.y + c4.z*h4.z + c4.w*h4.w;
            }
        }
        au += __shfl_xor_sync(~0u, au, 16);
        az += __shfl_xor_sync(~0u, az, 16);
        if (use_f) af += __shfl_xor_sync(~0u, af, 16);
        if (ih == 0) {
            float h  = hs[b*516 + j];
            float u  = xi + au;
            float f  = tanhf(u);
            float hl = h + dtj*(f - tauj*h);
            float z  = 1.f/(1.f+__expf(-(xz + az)));
            float hn2 = (1.f - z)*h + z*hl + af;
            __stcg(&g_h[(t & 1) ^ 1][(size_t)bg*Hn + j], hn2);
        }
        // prefetch next step's inputs so DRAM latency hides under the barrier
        if (t + 1 < Tn) {
            xi = xin[(size_t)(t+1)*Hn];
            xz = xzx[(size_t)(t+1)*Hn];
        }
        // 64-block grid barrier for this batch-half (release arrive, acquire exit)
        __syncthreads();
        if (tid == 0) {
            unsigned target = 64u * (unsigned)(t + 1);
            asm volatile("red.release.gpu.add.u32 [%0], %1;"
                         :: "l"(bar), "r"(1u) : "memory");
            unsigned v;
            do {
                asm volatile("ld.relaxed.gpu.u32 %0, [%1];" : "=r"(v) : "l"(bar));
            } while (v < target);
            asm volatile("fence.acq_rel.gpu;" ::: "memory");
        }
        __syncthreads();
    }
}

// pred_error_norm = sqrt(mean((h_last - h_prev)^2)); h_last=g_h[0], h_prev=g_h[1]
__global__ void k_pe(float* out) {
    __shared__ float sr[512];
    float s = 0.f;
    for (int i = threadIdx.x; i < Bn*Hn; i += 512) {
        float d = g_h[0][i] - g_h[1][i]; s += d*d;
    }
    sr[threadIdx.x] = s; __syncthreads();
    for (int o = 256; o; o >>= 1) {
        if (threadIdx.x < o) sr[threadIdx.x] += sr[threadIdx.x + o];
        __syncthreads();
    }
    if (threadIdx.x == 0)
        out[(size_t)Bn*Vn + (size_t)Bn*Hn] = sqrtf(sr[0] / (float)(Bn*Hn));
}

// LayerNorm of h_last -> g_hn and out[B*V ..]
__global__ void k_ln(const float* __restrict__ lng, const float* __restrict__ lnb,
                     float* out) {
    int b = blockIdx.x, j = threadIdx.x;
    __shared__ float sr[512];
    __shared__ float stat;
    float hv = g_h[0][b*Hn + j];
    sr[j] = hv; __syncthreads();
    for (int o = 256; o; o >>= 1) { if (j < o) sr[j] += sr[j+o]; __syncthreads(); }
    if (j == 0) stat = sr[0] / (float)Hn;
    __syncthreads();
    float mu = stat, d = hv - mu;
    __syncthreads();
    sr[j] = d*d; __syncthreads();
    for (int o = 256; o; o >>= 1) { if (j < o) sr[j] += sr[j+o]; __syncthreads(); }
    if (j == 0) stat = rsqrtf(sr[0] / (float)Hn + 1e-5f);
    __syncthreads();
    float y = d * stat * lng[j] + lnb[j];
    g_hn[b*Hn + j] = y;
    out[(size_t)Bn*Vn + b*Hn + j] = y;
}

// logits = g_hn @ Wlm^T + blm. grid (786, 2 bhalf) x 256 thr.
__global__ void k_logits(const float* __restrict__ Wlm, const float* __restrict__ blm,
                         float* out) {
    __shared__ float hs[16*516];
    int bh = blockIdx.y, tid = threadIdx.x, wid = tid >> 5, lane = tid & 31;
    int b = lane & 15, vh = lane >> 4;
#pragma unroll
    for (int m = 0; m < 32; m++) {
        int idx = tid + m*256;
        int bb = idx >> 9, k = idx & 511;
        hs[bb*516 + k] = g_hn[(bh*16 + bb)*Hn + k];
    }
    __syncthreads();
    const float4* H4 = (const float4*)(hs + b*516);
#pragma unroll
    for (int s = 0; s < 4; s++) {
        int v = blockIdx.x*64 + wid*8 + s*2 + vh;
        if (v < Vn) {
            const float4* W4 = (const float4*)(Wlm + (size_t)v*Hn);
            float acc = 0.f;
#pragma unroll 8
            for (int k4 = 0; k4 < 128; k4++) {
                float4 w = W4[k4], h = H4[k4];
                acc += w.x*h.x + w.y*h.y + w.z*h.z + w.w*h.w;
            }
            out[(size_t)(bh*16 + b)*Vn + v] = acc + blm[v];
        }
    }
}

extern "C" void kernel_launch(void* const* d_in, const int* in_sizes, int n_in,
                              void* d_out, int out_size) {
    const int*   ids  = (const int*)  d_in[0];
    const float* emb  = (const float*)d_in[1];
    const float* Wq   = (const float*)d_in[2];
    const float* Wk   = (const float*)d_in[3];
    const float* Wv   = (const float*)d_in[4];
    // d_in[5] = Wo (unused by forward)
    const float* Wg   = (const float*)d_in[6];
    const float* bg   = (const float*)d_in[7];
    const float* Win  = (const float*)d_in[8];
    const float* bin  = (const float*)d_in[9];
    const float* Wh   = (const float*)d_in[10];
    const float* ltau = (const float*)d_in[11];
    const float* ldt  = (const float*)d_in[12];
    const float* Wzx  = (const float*)d_in[13];
    const float* bzx  = (const float*)d_in[14];
    const float* Wzh  = (const float*)d_in[15];
    const float* fw   = (const float*)d_in[16];
    const float* lng  = (const float*)d_in[17];
    const float* lnb  = (const float*)d_in[18];
    const float* Wlm  = (const float*)d_in[19];
    const float* blm  = (const float*)d_in[20];
    float* out = (float*)d_out;

    static int smem_set = 0;
    const int recur_smem = (12288 + 16*516) * 4;   // 82,176 bytes
    if (!smem_set) {
        cudaFuncSetAttribute(k_recur, cudaFuncAttributeMaxDynamicSharedMemorySize,
                             recur_smem);
        smem_set = 1;
    }

    k_init<<<64, 256>>>();
    k_embed<<<BTn, 128>>>(ids, emb);

    dim3 gp(BTn/128, 4);
    k_proj<<<gp, 256>>>(0, Wq, nullptr, 1);   // q = phi(x Wq^T)
    k_proj<<<gp, 256>>>(1, Wk, nullptr, 1);   // k = phi(x Wk^T)
    k_proj<<<gp, 256>>>(2, Wv, nullptr, 0);   // v
    k_proj<<<gp, 256>>>(3, Wg, bg,      2);   // gate = sigmoid(x Wg^T + bg)

    k_rkv<<<dim3(4, 32), 128>>>();
    k_attn<<<BTn, 256>>>();                   // x2 -> g_x (in place)

    k_proj<<<gp, 256>>>(0, Win, bin, 0);      // xin -> g_q
    k_proj<<<gp, 256>>>(1, Wzx, bzx, 0);      // xzx -> g_k
    k_prep<<<1024, 256>>>(fw, ldt, ltau);

    k_recur<<<128, 256, recur_smem>>>(Wh, Wzh);

    k_ln<<<32, 512>>>(lng, lnb, out);
    k_pe<<<1, 512>>>(out);
    k_logits<<<dim3(786, 2), 256>>>(Wlm, blm, out);
}

// round 11
// speedup vs baseline: 1.5859x; 1.0271x over previous
#include <cuda_runtime.h>
#include <math.h>

#define Bn 32
#define Tn 2048
#define Vn 50257
#define Dn 512
#define Hn 512
#define BTn (Bn*Tn)

typedef unsigned long long ull;
#define FMA2(acc, a, b) asm("fma.rn.f32x2 %0, %1, %2, %0;" : "+l"(acc) : "l"(a), "l"(b))

// ------- scratch (__device__ globals: allocation-free) -------
__device__ float g_x[(size_t)BTn*Dn];   // x, then x2 in place
__device__ float g_q[(size_t)BTn*Dn];   // q, then xin
__device__ float g_k[(size_t)BTn*Dn];   // k, then xzx
__device__ float g_v[(size_t)BTn*Dn];
__device__ float g_g[(size_t)BTn*Dn];
__device__ float g_ks[Bn*Dn];
__device__ float g_kvs[Bn*Dn];
__device__ float g_h[2][Bn*Hn];
__device__ float g_hn[Bn*Hn];
__device__ float g_fT[Hn*Hn];
__device__ float g_dt[Hn];
__device__ float g_tau[Hn];
__device__ unsigned g_barrier[2];
__device__ unsigned g_fw_nz;

__global__ void k_init() {
    int i = blockIdx.x * 256 + threadIdx.x;
    if (i < Bn*Hn) { g_h[0][i] = 0.f; g_ks[i] = 0.f; g_kvs[i] = 0.f; }
    if (i < 2) g_barrier[i] = 0u;
    if (i == 2) g_fw_nz = 0u;
}

__global__ void k_embed(const int* __restrict__ ids, const float* __restrict__ emb) {
    int bt = blockIdx.x;
    int id = ids[bt];
    ((float4*)(g_x + (size_t)bt * Dn))[threadIdx.x] =
        ((const float4*)(emb + (size_t)id * Dn))[threadIdx.x];
}

// C[m,n] = act( sum_k X[m,k]*W[n,k] + bias[n] ), X = g_x always.
__global__ __launch_bounds__(256,2) void k_proj(int osel, const float* __restrict__ W,
                                                const float* __restrict__ bias, int act) {
    float* outp = (osel==0)?g_q:(osel==1)?g_k:(osel==2)?g_v:g_g;
    __shared__ float As[8][132];
    __shared__ float Bs[8][132];
    int tid = threadIdx.x;
    int tx = tid & 15, ty = tid >> 4;
    int m0 = blockIdx.x * 128, n0 = blockIdx.y * 128;
    int lrow = tid >> 1, lcol = (tid & 1) * 4;
    const float* Ap = g_x + (size_t)(m0 + lrow) * Dn + lcol;
    const float* Bp = W   + (size_t)(n0 + lrow) * Dn + lcol;
    float acc[8][8];
#pragma unroll
    for (int i = 0; i < 8; i++)
#pragma unroll
        for (int j = 0; j < 8; j++) acc[i][j] = 0.f;
    for (int kt = 0; kt < 64; kt++) {
        float4 av = *(const float4*)(Ap + kt*8);
        float4 bv = *(const float4*)(Bp + kt*8);
        __syncthreads();
        As[lcol+0][lrow]=av.x; As[lcol+1][lrow]=av.y; As[lcol+2][lrow]=av.z; As[lcol+3][lrow]=av.w;
        Bs[lcol+0][lrow]=bv.x; Bs[lcol+1][lrow]=bv.y; Bs[lcol+2][lrow]=bv.z; Bs[lcol+3][lrow]=bv.w;
        __syncthreads();
#pragma unroll
        for (int kk = 0; kk < 8; kk++) {
            float a[8], b[8];
            *(float4*)(a)   = *(const float4*)&As[kk][ty*8];
            *(float4*)(a+4) = *(const float4*)&As[kk][ty*8+4];
            *(float4*)(b)   = *(const float4*)&Bs[kk][tx*8];
            *(float4*)(b+4) = *(const float4*)&Bs[kk][tx*8+4];
#pragma unroll
            for (int i = 0; i < 8; i++)
#pragma unroll
                for (int j = 0; j < 8; j++) acc[i][j] += a[i]*b[j];
        }
    }
#pragma unroll
    for (int i = 0; i < 8; i++) {
        int m = m0 + ty*8 + i;
#pragma unroll
        for (int j = 0; j < 8; j++) {
            int n = n0 + tx*8 + j;
            float c = acc[i][j];
            if (bias) c += bias[n];
            if (act == 1)      c = (c > 0.f) ? (c + 1.f) : __expf(c);
            else if (act == 2) c = 1.f / (1.f + __expf(-c));
            outp[(size_t)m * Dn + n] = c;
        }
    }
}

__global__ void k_rkv() {
    int b = blockIdx.y, n = blockIdx.x*128 + threadIdx.x;
    const float* Kp = g_k + (size_t)b*Tn*Dn + n;
    const float* Vp = g_v + (size_t)b*Tn*Dn + n;
    float sk = 0.f, sv = 0.f;
#pragma unroll 8
    for (int t = 0; t < Tn; t++) {
        float kk = Kp[(size_t)t*Dn];
        float vv = Vp[(size_t)t*Dn];
        sk += kk; sv += kk*vv;
    }
    g_ks[b*Dn+n] = sk; g_kvs[b*Dn+n] = sv;
}

__global__ void k_attn() {
    int bt = blockIdx.x, b = bt >> 11;
    int tid = threadIdx.x, wid = tid >> 5, lane = tid & 31;
    __shared__ float sp[8][4];
    __shared__ float sf[4];
    const float* qr  = g_q + (size_t)bt*Dn;
    const float* ks  = g_ks  + b*Dn;
    const float* kvs = g_kvs + b*Dn;
    float q0 = qr[tid], q1 = qr[tid+256];
    float pn0 = q0*kvs[tid],     pd0 = q0*ks[tid];
    float pn1 = q1*kvs[tid+256], pd1 = q1*ks[tid+256];
#pragma unroll
    for (int o = 16; o; o >>= 1) {
        pn0 += __shfl_xor_sync(~0u,pn0,o); pd0 += __shfl_xor_sync(~0u,pd0,o);
        pn1 += __shfl_xor_sync(~0u,pn1,o); pd1 += __shfl_xor_sync(~0u,pd1,o);
    }
    if (lane == 0) { sp[wid][0]=pn0; sp[wid][1]=pd0; sp[wid][2]=pn1; sp[wid][3]=pd1; }
    __syncthreads();
    if (tid == 0) {
        float a=0,c=0,d=0,e=0;
        for (int w = 0; w < 8; w++) { a+=sp[w][0]; c+=sp[w][1]; d+=sp[w][2]; e+=sp[w][3]; }
        sf[0]=a; sf[1]=c; sf[2]=d; sf[3]=e;
    }
    __syncthreads();
    float s0 = sf[0] / (sf[1] + 1e-6f);
    float s1 = sf[2] / (sf[3] + 1e-6f);
    float* xr = g_x + (size_t)bt*Dn;
    const float* gr = g_g + (size_t)bt*Dn;
    float ga = gr[tid],   xa = xr[tid];
    float gb = gr[tid+256], xb = xr[tid+256];
    xr[tid]     = ga*s0 + (1.f-ga)*xa;
    xr[tid+256] = gb*s1 + (1.f-gb)*xb;
}

__global__ void k_prep(const float* __restrict__ fw, const float* __restrict__ ldt,
                       const float* __restrict__ ltau) {
    int i = blockIdx.x*256 + threadIdx.x;
    int r = i >> 9, c = i & 511;
    float v = fw[i];
    g_fT[c*Hn + r] = v;
    if (v != 0.f) atomicOr(&g_fw_nz, 1u);
    if (i < Hn) { g_dt[i] = expf(ldt[i]); g_tau[i] = expf(ltau[i]); }
}

// Persistent recurrence: 128 blocks = 64 j-chunks x 2 batch-halves, 256 thr
// = 8 warps, warp = one j. Lane l owns k in [16l, 16l+16): its W_h/W_zh
// (and fast_W^T when nonzero) slices live in REGISTERS (zero per-step weight
// crossbar traffic). h staged once per block into a pad-swizzled layout
// (p(k)=k+(k>>4)*4) giving conflict-free LDS.128 per lane-chunk. Dots use
// packed fma.rn.f32x2 over (k,k+1) pairs; per-b partials reduced via a
// conflict-free SMEM transpose.
__global__ __launch_bounds__(256) void k_recur(const float* __restrict__ Wh,
                                               const float* __restrict__ Wz) {
    extern __shared__ float sm[];
    float* hs  = sm;                 // [16][640] = 40960B (swizzle-padded)
    float* red = sm + 16*640;        // 8 warps x [32][33] = 33792B
    int bh = blockIdx.x & 1, jc = blockIdx.x >> 1;
    int tid = threadIdx.x, wid = tid >> 5, lane = tid & 31;
    int j = jc*8 + wid;
    unsigned use_f = g_fw_nz;
    float dtj = g_dt[j], tauj = g_tau[j];

    // per-lane weight registers (k-chunk [lane*16, lane*16+16), packed pairs)
    ull wu[8], wz[8], wf[8];
    {
        const ull* pu = (const ull*)(Wh   + (size_t)j*Hn + lane*16);
        const ull* pz = (const ull*)(Wz   + (size_t)j*Hn + lane*16);
        const ull* pf = (const ull*)(g_fT + (size_t)j*Hn + lane*16);
#pragma unroll
        for (int p = 0; p < 8; p++) {
            wu[p] = pu[p]; wz[p] = pz[p];
            wf[p] = use_f ? pf[p] : 0ull;
        }
    }
    int lane_off = lane*20;          // phys start of this lane's k-chunk
    int jsw = j + ((j >> 4) << 2);   // phys index of h[b][j]
    float* rw = red + wid*(32*33);
    unsigned* bar = &g_barrier[bh];

    // per-lane (lanes<16) hoisted-input pointers; clamp others harmlessly
    int bgl = bh*16 + (lane & 15);
    const float* xin = g_q + (size_t)bgl*Tn*Hn + j;
    const float* xzx = g_k + (size_t)bgl*Tn*Hn + j;
    float xi = 0.f, xz = 0.f;
    if (lane < 16) { xi = xin[0]; xz = xzx[0]; }

    for (int t = 0; t < Tn; t++) {
        // stage h (coalesced LDG.128 -> swizzled STS.128)
        const float4* hp = (const float4*)(g_h[t & 1] + (size_t)bh*16*Hn);
#pragma unroll
        for (int m = 0; m < 8; m++) {
            int idx = tid + m*256;          // b(4b) * 128 + k4(7b)
            int b = idx >> 7, k4 = idx & 127;
            float4 hv = __ldcg(hp + idx);
            *(float4*)(hs + b*640 + k4*4 + ((k4 >> 2) << 2)) = hv;
        }
        __syncthreads();

        // accumulate: for each batch b, partial dots over this lane's k-chunk
        ull au[16], az[16], af[16];
#pragma unroll
        for (int b = 0; b < 16; b++) { au[b]=0ull; az[b]=0ull; af[b]=0ull; }
#pragma unroll
        for (int b = 0; b < 16; b++) {
            const ulonglong2* h2 = (const ulonglong2*)(hs + b*640 + lane_off);
            ulonglong2 hA = h2[0], hB = h2[1];
            FMA2(au[b], wu[0], hA.x); FMA2(az[b], wz[0], hA.x);
            FMA2(au[b], wu[1], hA.y); FMA2(az[b], wz[1], hA.y);
            FMA2(au[b], wu[2], hB.x); FMA2(az[b], wz[2], hB.x);
            FMA2(au[b], wu[3], hB.y); FMA2(az[b], wz[3], hB.y);
            ulonglong2 hC = h2[2], hD = h2[3];
            FMA2(au[b], wu[4], hC.x); FMA2(az[b], wz[4], hC.x);
            FMA2(au[b], wu[5], hC.y); FMA2(az[b], wz[5], hC.y);
            FMA2(au[b], wu[6], hD.x); FMA2(az[b], wz[6], hD.x);
            FMA2(au[b], wu[7], hD.y); FMA2(az[b], wz[7], hD.y);
            if (use_f) {
                FMA2(af[b], wf[0], hA.x); FMA2(af[b], wf[1], hA.y);
                FMA2(af[b], wf[2], hB.x); FMA2(af[b], wf[3], hB.y);
                FMA2(af[b], wf[4], hC.x); FMA2(af[b], wf[5], hC.y);
                FMA2(af[b], wf[6], hD.x); FMA2(af[b], wf[7], hD.y);
            }
        }

        // cross-lane reduce via SMEM transpose: rows 0..15 = au, 16..31 = az
#pragma unroll
        for (int v = 0; v < 16; v++) {
            unsigned lo, hi;
            asm("mov.b64 {%0,%1}, %2;" : "=r"(lo), "=r"(hi) : "l"(au[v]));
            rw[v*33 + lane] = __uint_as_float(lo) + __uint_as_float(hi);
            asm("mov.b64 {%0,%1}, %2;" : "=r"(lo), "=r"(hi) : "l"(az[v]));
            rw[(16+v)*33 + lane] = __uint_as_float(lo) + __uint_as_float(hi);
        }
        __syncwarp();
        float s = 0.f;
#pragma unroll
        for (int i = 0; i < 32; i++) s += rw[lane*33 + i];
        float other = __shfl_xor_sync(~0u, s, 16);   // lanes<16: s=au[b], other=az[b]

        float sf = 0.f;
        if (use_f) {
            __syncwarp();
#pragma unroll
            for (int v = 0; v < 16; v++) {
                unsigned lo, hi;
                asm("mov.b64 {%0,%1}, %2;" : "=r"(lo), "=r"(hi) : "l"(af[v]));
                rw[v*33 + lane] = __uint_as_float(lo) + __uint_as_float(hi);
            }
            __syncwarp();
            if (lane < 16)
#pragma unroll
                for (int i = 0; i < 32; i++) sf += rw[lane*33 + i];
        }

        if (lane < 16) {
            int b = lane, bg = bh*16 + b;
            float h  = hs[b*640 + jsw];
            float u  = xi + s;
            float f  = tanhf(u);
            float hl = h + dtj*(f - tauj*h);
            float z  = 1.f/(1.f+__expf(-(xz + other)));
            float hn2 = (1.f - z)*h + z*hl + sf;
            __stcg(&g_h[(t & 1) ^ 1][(size_t)bg*Hn + j], hn2);
            if (t + 1 < Tn) {   // prefetch next step's hoisted inputs
                xi = xin[(size_t)(t+1)*Hn];
                xz = xzx[(size_t)(t+1)*Hn];
            }
        }
        // 64-block grid barrier for this batch-half
        __syncthreads();
        if (tid == 0) {
            unsigned target = 64u * (unsigned)(t + 1);
            asm volatile("red.release.gpu.add.u32 [%0], %1;"
                         :: "l"(bar), "r"(1u) : "memory");
            unsigned v;
            do {
                asm volatile("ld.relaxed.gpu.u32 %0, [%1];" : "=r"(v) : "l"(bar));
            } while (v < target);
            asm volatile("fence.acq_rel.gpu;" ::: "memory");
        }
        __syncthreads();
    }
}

__global__ void k_pe(float* out) {
    __shared__ float sr[512];
    float s = 0.f;
    for (int i = threadIdx.x; i < Bn*Hn; i += 512) {
        float d = g_h[0][i] - g_h[1][i]; s += d*d;
    }
    sr[threadIdx.x] = s; __syncthreads();
    for (int o = 256; o; o >>= 1) {
        if (threadIdx.x < o) sr[threadIdx.x] += sr[threadIdx.x + o];
        __syncthreads();
    }
    if (threadIdx.x == 0)
        out[(size_t)Bn*Vn + (size_t)Bn*Hn] = sqrtf(sr[0] / (float)(Bn*Hn));
}

__global__ void k_ln(const float* __restrict__ lng, const float* __restrict__ lnb,
                     float* out) {
    int b = blockIdx.x, j = threadIdx.x;
    __shared__ float sr[512];
    __shared__ float stat;
    float hv = g_h[0][b*Hn + j];
    sr[j] = hv; __syncthreads();
    for (int o = 256; o; o >>= 1) { if (j < o) sr[j] += sr[j+o]; __syncthreads(); }
    if (j == 0) stat = sr[0] / (float)Hn;
    __syncthreads();
    float mu = stat, d = hv - mu;
    __syncthreads();
    sr[j] = d*d; __syncthreads();
    for (int o = 256; o; o >>= 1) { if (j < o) sr[j] += sr[j+o]; __syncthreads(); }
    if (j == 0) stat = rsqrtf(sr[0] / (float)Hn + 1e-5f);
    __syncthreads();
    float y = d * stat * lng[j] + lnb[j];
    g_hn[b*Hn + j] = y;
    out[(size_t)Bn*Vn + b*Hn + j] = y;
}

__global__ void k_logits(const float* __restrict__ Wlm, const float* __restrict__ blm,
                         float* out) {
    __shared__ float hs[16*516];
    int bh = blockIdx.y, tid = threadIdx.x, wid = tid >> 5, lane = tid & 31;
    int b = lane & 15, vh = lane >> 4;
#pragma unroll
    for (int m = 0; m < 32; m++) {
        int idx = tid + m*256;
        int bb = idx >> 9, k = idx & 511;
        hs[bb*516 + k] = g_hn[(bh*16 + bb)*Hn + k];
    }
    __syncthreads();
    const float4* H4 = (const float4*)(hs + b*516);
#pragma unroll
    for (int s = 0; s < 4; s++) {
        int v = blockIdx.x*64 + wid*8 + s*2 + vh;
        if (v < Vn) {
            const float4* W4 = (const float4*)(Wlm + (size_t)v*Hn);
            float acc = 0.f;
#pragma unroll 8
            for (int k4 = 0; k4 < 128; k4++) {
                float4 w = W4[k4], h = H4[k4];
                acc += w.x*h.x + w.y*h.y + w.z*h.z + w.w*h.w;
            }
            out[(size_t)(bh*16 + b)*Vn + v] = acc + blm[v];
        }
    }
}

extern "C" void kernel_launch(void* const* d_in, const int* in_sizes, int n_in,
                              void* d_out, int out_size) {
    const int*   ids  = (const int*)  d_in[0];
    const float* emb  = (const float*)d_in[1];
    const float* Wq   = (const float*)d_in[2];
    const float* Wk   = (const float*)d_in[3];
    const float* Wv   = (const float*)d_in[4];
    const float* Wg   = (const float*)d_in[6];
    const float* bg   = (const float*)d_in[7];
    const float* Win  = (const float*)d_in[8];
    const float* bin  = (const float*)d_in[9];
    const float* Wh   = (const float*)d_in[10];
    const float* ltau = (const float*)d_in[11];
    const float* ldt  = (const float*)d_in[12];
    const float* Wzx  = (const float*)d_in[13];
    const float* bzx  = (const float*)d_in[14];
    const float* Wzh  = (const float*)d_in[15];
    const float* fw   = (const float*)d_in[16];
    const float* lng  = (const float*)d_in[17];
    const float* lnb  = (const float*)d_in[18];
    const float* Wlm  = (const float*)d_in[19];
    const float* blm  = (const float*)d_in[20];
    float* out = (float*)d_out;

    static int smem_set = 0;
    const int recur_smem = (16*640 + 8*32*33) * 4;   // 74,752 bytes
    if (!smem_set) {
        cudaFuncSetAttribute(k_recur, cudaFuncAttributeMaxDynamicSharedMemorySize,
                             recur_smem);
        smem_set = 1;
    }

    k_init<<<64, 256>>>();
    k_embed<<<BTn, 128>>>(ids, emb);

    dim3 gp(BTn/128, 4);
    k_proj<<<gp, 256>>>(0, Wq, nullptr, 1);   // q = phi(x Wq^T)
    k_proj<<<gp, 256>>>(1, Wk, nullptr, 1);   // k = phi(x Wk^T)
    k_proj<<<gp, 256>>>(2, Wv, nullptr, 0);   // v
    k_proj<<<gp, 256>>>(3, Wg, bg,      2);   // gate

    k_rkv<<<dim3(4, 32), 128>>>();
    k_attn<<<BTn, 256>>>();                   // x2 -> g_x (in place)

    k_proj<<<gp, 256>>>(0, Win, bin, 0);      // xin -> g_q
    k_proj<<<gp, 256>>>(1, Wzx, bzx, 0);      // xzx -> g_k
    k_prep<<<1024, 256>>>(fw, ldt, ltau);

    k_recur<<<128, 256, recur_smem>>>(Wh, Wzh);

    k_ln<<<32, 512>>>(lng, lnb, out);
    k_pe<<<1, 512>>>(out);
    k_logits<<<dim3(786, 2), 256>>>(Wlm, blm, out);
}

// round 12
// speedup vs baseline: 1.6219x; 1.0227x over previous
#include <cuda_runtime.h>
#include <math.h>

#define Bn 32
#define Tn 2048
#define Vn 50257
#define Dn 512
#define Hn 512
#define BTn (Bn*Tn)

typedef unsigned long long ull;
#define FMA2(acc, a, b) asm("fma.rn.f32x2 %0, %1, %2, %0;" : "+l"(acc) : "l"(a), "l"(b))

// ------- scratch (__device__ globals: allocation-free) -------
__device__ float g_x[(size_t)BTn*Dn];   // x, then x2 in place
__device__ float g_q[(size_t)BTn*Dn];   // q, then xin
__device__ float g_k[(size_t)BTn*Dn];   // k, then xzx
__device__ float g_v[(size_t)BTn*Dn];
__device__ float g_g[(size_t)BTn*Dn];
__device__ float g_ks[Bn*Dn];
__device__ float g_kvs[Bn*Dn];
__device__ float g_h[2][Bn*Hn];
__device__ float g_hn[Bn*Hn];
__device__ float g_fT[Hn*Hn];
__device__ float g_dt[Hn];
__device__ float g_tau[Hn];
__device__ unsigned g_barrier[2];
__device__ unsigned g_fw_nz;

__global__ void k_init() {
    int i = blockIdx.x * 256 + threadIdx.x;
    if (i < Bn*Hn) { g_h[0][i] = 0.f; g_ks[i] = 0.f; g_kvs[i] = 0.f; }
    if (i < 2) g_barrier[i] = 0u;
    if (i == 2) g_fw_nz = 0u;
}

__global__ void k_embed(const int* __restrict__ ids, const float* __restrict__ emb) {
    int bt = blockIdx.x;
    int id = ids[bt];
    ((float4*)(g_x + (size_t)bt * Dn))[threadIdx.x] =
        ((const float4*)(emb + (size_t)id * Dn))[threadIdx.x];
}

// C[m,n] = act( sum_k X[m,k]*W[n,k] + bias[n] ), X = g_x always.
// 128x128 tile, K-tile 8, 256 thr, 8x8/thread via packed fma.rn.f32x2
// (j-pairs in 64-bit accumulators). osel: 0 q,1 k,2 v,3 g.
__global__ __launch_bounds__(256,2) void k_proj(int osel, const float* __restrict__ W,
                                                const float* __restrict__ bias, int act) {
    float* outp = (osel==0)?g_q:(osel==1)?g_k:(osel==2)?g_v:g_g;
    __shared__ __align__(16) float As[8][132];
    __shared__ __align__(16) float Bs[8][132];
    int tid = threadIdx.x;
    int tx = tid & 15, ty = tid >> 4;
    int m0 = blockIdx.x * 128, n0 = blockIdx.y * 128;
    int lrow = tid >> 1, lcol = (tid & 1) * 4;
    const float* Ap = g_x + (size_t)(m0 + lrow) * Dn + lcol;
    const float* Bp = W   + (size_t)(n0 + lrow) * Dn + lcol;
    ull acc2[8][4];
#pragma unroll
    for (int i = 0; i < 8; i++)
#pragma unroll
        for (int jp = 0; jp < 4; jp++) acc2[i][jp] = 0ull;
    for (int kt = 0; kt < 64; kt++) {
        float4 av = *(const float4*)(Ap + kt*8);
        float4 bv = *(const float4*)(Bp + kt*8);
        __syncthreads();
        As[lcol+0][lrow]=av.x; As[lcol+1][lrow]=av.y; As[lcol+2][lrow]=av.z; As[lcol+3][lrow]=av.w;
        Bs[lcol+0][lrow]=bv.x; Bs[lcol+1][lrow]=bv.y; Bs[lcol+2][lrow]=bv.z; Bs[lcol+3][lrow]=bv.w;
        __syncthreads();
#pragma unroll
        for (int kk = 0; kk < 8; kk++) {
            float a[8];
            *(float4*)(a)   = *(const float4*)&As[kk][ty*8];
            *(float4*)(a+4) = *(const float4*)&As[kk][ty*8+4];
            ulonglong2 bA = *(const ulonglong2*)&Bs[kk][tx*8];
            ulonglong2 bB = *(const ulonglong2*)&Bs[kk][tx*8+4];
#pragma unroll
            for (int i = 0; i < 8; i++) {
                ull as_;
                asm("mov.b64 %0, {%1,%1};" : "=l"(as_) : "f"(a[i]));
                FMA2(acc2[i][0], as_, bA.x);
                FMA2(acc2[i][1], as_, bA.y);
                FMA2(acc2[i][2], as_, bB.x);
                FMA2(acc2[i][3], as_, bB.y);
            }
        }
    }
#pragma unroll
    for (int i = 0; i < 8; i++) {
        int m = m0 + ty*8 + i;
#pragma unroll
        for (int jp = 0; jp < 4; jp++) {
            int n = n0 + tx*8 + jp*2;
            float c0, c1;
            asm("mov.b64 {%0,%1}, %2;" : "=f"(c0), "=f"(c1) : "l"(acc2[i][jp]));
            if (bias) { c0 += bias[n]; c1 += bias[n+1]; }
            if (act == 1) {
                c0 = (c0 > 0.f) ? (c0 + 1.f) : __expf(c0);
                c1 = (c1 > 0.f) ? (c1 + 1.f) : __expf(c1);
            } else if (act == 2) {
                c0 = 1.f / (1.f + __expf(-c0));
                c1 = 1.f / (1.f + __expf(-c1));
            }
            *(float2*)(outp + (size_t)m * Dn + n) = make_float2(c0, c1);
        }
    }
}

__global__ void k_rkv() {
    int b = blockIdx.y, n = blockIdx.x*128 + threadIdx.x;
    const float* Kp = g_k + (size_t)b*Tn*Dn + n;
    const float* Vp = g_v + (size_t)b*Tn*Dn + n;
    float sk = 0.f, sv = 0.f;
#pragma unroll 8
    for (int t = 0; t < Tn; t++) {
        float kk = Kp[(size_t)t*Dn];
        float vv = Vp[(size_t)t*Dn];
        sk += kk; sv += kk*vv;
    }
    g_ks[b*Dn+n] = sk; g_kvs[b*Dn+n] = sv;
}

__global__ void k_attn() {
    int bt = blockIdx.x, b = bt >> 11;
    int tid = threadIdx.x, wid = tid >> 5, lane = tid & 31;
    __shared__ float sp[8][4];
    __shared__ float sf[4];
    const float* qr  = g_q + (size_t)bt*Dn;
    const float* ks  = g_ks  + b*Dn;
    const float* kvs = g_kvs + b*Dn;
    float q0 = qr[tid], q1 = qr[tid+256];
    float pn0 = q0*kvs[tid],     pd0 = q0*ks[tid];
    float pn1 = q1*kvs[tid+256], pd1 = q1*ks[tid+256];
#pragma unroll
    for (int o = 16; o; o >>= 1) {
        pn0 += __shfl_xor_sync(~0u,pn0,o); pd0 += __shfl_xor_sync(~0u,pd0,o);
        pn1 += __shfl_xor_sync(~0u,pn1,o); pd1 += __shfl_xor_sync(~0u,pd1,o);
    }
    if (lane == 0) { sp[wid][0]=pn0; sp[wid][1]=pd0; sp[wid][2]=pn1; sp[wid][3]=pd1; }
    __syncthreads();
    if (tid == 0) {
        float a=0,c=0,d=0,e=0;
        for (int w = 0; w < 8; w++) { a+=sp[w][0]; c+=sp[w][1]; d+=sp[w][2]; e+=sp[w][3]; }
        sf[0]=a; sf[1]=c; sf[2]=d; sf[3]=e;
    }
    __syncthreads();
    float s0 = sf[0] / (sf[1] + 1e-6f);
    float s1 = sf[2] / (sf[3] + 1e-6f);
    float* xr = g_x + (size_t)bt*Dn;
    const float* gr = g_g + (size_t)bt*Dn;
    float ga = gr[tid],   xa = xr[tid];
    float gb = gr[tid+256], xb = xr[tid+256];
    xr[tid]     = ga*s0 + (1.f-ga)*xa;
    xr[tid+256] = gb*s1 + (1.f-gb)*xb;
}

__global__ void k_prep(const float* __restrict__ fw, const float* __restrict__ ldt,
                       const float* __restrict__ ltau) {
    int i = blockIdx.x*256 + threadIdx.x;
    int r = i >> 9, c = i & 511;
    float v = fw[i];
    g_fT[c*Hn + r] = v;
    if (v != 0.f) atomicOr(&g_fw_nz, 1u);
    if (i < Hn) { g_dt[i] = expf(ldt[i]); g_tau[i] = expf(ltau[i]); }
}

// Persistent recurrence: 128 blocks = 64 j-chunks x 2 batch-halves, 256 thr
// = 8 warps, warp = one j. Lane l owns k in [16l, 16l+16): W_h/W_zh slices
// in registers; h staged pad-swizzled (conflict-free LDS.128); packed f32x2
// dots; per-b partials reduced via conflict-free SMEM transpose.
__global__ __launch_bounds__(256) void k_recur(const float* __restrict__ Wh,
                                               const float* __restrict__ Wz) {
    extern __shared__ float sm[];
    float* hs  = sm;                 // [16][640] (swizzle-padded)
    float* red = sm + 16*640;        // 8 warps x [32][33]
    int bh = blockIdx.x & 1, jc = blockIdx.x >> 1;
    int tid = threadIdx.x, wid = tid >> 5, lane = tid & 31;
    int j = jc*8 + wid;
    unsigned use_f = g_fw_nz;
    float dtj = g_dt[j], tauj = g_tau[j];

    ull wu[8], wz[8], wf[8];
    {
        const ull* pu = (const ull*)(Wh   + (size_t)j*Hn + lane*16);
        const ull* pz = (const ull*)(Wz   + (size_t)j*Hn + lane*16);
        const ull* pf = (const ull*)(g_fT + (size_t)j*Hn + lane*16);
#pragma unroll
        for (int p = 0; p < 8; p++) {
            wu[p] = pu[p]; wz[p] = pz[p];
            wf[p] = use_f ? pf[p] : 0ull;
        }
    }
    int lane_off = lane*20;
    int jsw = j + ((j >> 4) << 2);
    float* rw = red + wid*(32*33);
    unsigned* bar = &g_barrier[bh];

    int bgl = bh*16 + (lane & 15);
    const float* xin = g_q + (size_t)bgl*Tn*Hn + j;
    const float* xzx = g_k + (size_t)bgl*Tn*Hn + j;
    float xi = 0.f, xz = 0.f;
    if (lane < 16) { xi = xin[0]; xz = xzx[0]; }

    for (int t = 0; t < Tn; t++) {
        const float4* hp = (const float4*)(g_h[t & 1] + (size_t)bh*16*Hn);
#pragma unroll
        for (int m = 0; m < 8; m++) {
            int idx = tid + m*256;
            int b = idx >> 7, k4 = idx & 127;
            float4 hv = __ldcg(hp + idx);
            *(float4*)(hs + b*640 + k4*4 + ((k4 >> 2) << 2)) = hv;
        }
        __syncthreads();

        ull au[16], az[16], af[16];
#pragma unroll
        for (int b = 0; b < 16; b++) { au[b]=0ull; az[b]=0ull; af[b]=0ull; }
#pragma unroll
        for (int b = 0; b < 16; b++) {
            const ulonglong2* h2 = (const ulonglong2*)(hs + b*640 + lane_off);
            ulonglong2 hA = h2[0], hB = h2[1];
            FMA2(au[b], wu[0], hA.x); FMA2(az[b], wz[0], hA.x);
            FMA2(au[b], wu[1], hA.y); FMA2(az[b], wz[1], hA.y);
            FMA2(au[b], wu[2], hB.x); FMA2(az[b], wz[2], hB.x);
            FMA2(au[b], wu[3], hB.y); FMA2(az[b], wz[3], hB.y);
            ulonglong2 hC = h2[2], hD = h2[3];
            FMA2(au[b], wu[4], hC.x); FMA2(az[b], wz[4], hC.x);
            FMA2(au[b], wu[5], hC.y); FMA2(az[b], wz[5], hC.y);
            FMA2(au[b], wu[6], hD.x); FMA2(az[b], wz[6], hD.x);
            FMA2(au[b], wu[7], hD.y); FMA2(az[b], wz[7], hD.y);
            if (use_f) {
                FMA2(af[b], wf[0], hA.x); FMA2(af[b], wf[1], hA.y);
                FMA2(af[b], wf[2], hB.x); FMA2(af[b], wf[3], hB.y);
                FMA2(af[b], wf[4], hC.x); FMA2(af[b], wf[5], hC.y);
                FMA2(af[b], wf[6], hD.x); FMA2(af[b], wf[7], hD.y);
            }
        }

#pragma unroll
        for (int v = 0; v < 16; v++) {
            unsigned lo, hi;
            asm("mov.b64 {%0,%1}, %2;" : "=r"(lo), "=r"(hi) : "l"(au[v]));
            rw[v*33 + lane] = __uint_as_float(lo) + __uint_as_float(hi);
            asm("mov.b64 {%0,%1}, %2;" : "=r"(lo), "=r"(hi) : "l"(az[v]));
            rw[(16+v)*33 + lane] = __uint_as_float(lo) + __uint_as_float(hi);
        }
        __syncwarp();
        float s = 0.f;
#pragma unroll
        for (int i = 0; i < 32; i++) s += rw[lane*33 + i];
        float other = __shfl_xor_sync(~0u, s, 16);

        float sfv = 0.f;
        if (use_f) {
            __syncwarp();
#pragma unroll
            for (int v = 0; v < 16; v++) {
                unsigned lo, hi;
                asm("mov.b64 {%0,%1}, %2;" : "=r"(lo), "=r"(hi) : "l"(af[v]));
                rw[v*33 + lane] = __uint_as_float(lo) + __uint_as_float(hi);
            }
            __syncwarp();
            if (lane < 16)
#pragma unroll
                for (int i = 0; i < 32; i++) sfv += rw[lane*33 + i];
        }

        if (lane < 16) {
            int b = lane, bg = bh*16 + b;
            float h  = hs[b*640 + jsw];
            float u  = xi + s;
            float f  = tanhf(u);
            float hl = h + dtj*(f - tauj*h);
            float z  = 1.f/(1.f+__expf(-(xz + other)));
            float hn2 = (1.f - z)*h + z*hl + sfv;
            __stcg(&g_h[(t & 1) ^ 1][(size_t)bg*Hn + j], hn2);
            if (t + 1 < Tn) {
                xi = xin[(size_t)(t+1)*Hn];
                xz = xzx[(size_t)(t+1)*Hn];
            }
        }
        __syncthreads();
        if (tid == 0) {
            unsigned target = 64u * (unsigned)(t + 1);
            asm volatile("red.release.gpu.add.u32 [%0], %1;"
                         :: "l"(bar), "r"(1u) : "memory");
            unsigned v;
            do {
                asm volatile("ld.relaxed.gpu.u32 %0, [%1];" : "=r"(v) : "l"(bar));
            } while (v < target);
            asm volatile("fence.acq_rel.gpu;" ::: "memory");
        }
        __syncthreads();
    }
}

__global__ void k_pe(float* out) {
    __shared__ float sr[512];
    float s = 0.f;
    for (int i = threadIdx.x; i < Bn*Hn; i += 512) {
        float d = g_h[0][i] - g_h[1][i]; s += d*d;
    }
    sr[threadIdx.x] = s; __syncthreads();
    for (int o = 256; o; o >>= 1) {
        if (threadIdx.x < o) sr[threadIdx.x] += sr[threadIdx.x + o];
        __syncthreads();
    }
    if (threadIdx.x == 0)
        out[(size_t)Bn*Vn + (size_t)Bn*Hn] = sqrtf(sr[0] / (float)(Bn*Hn));
}

__global__ void k_ln(const float* __restrict__ lng, const float* __restrict__ lnb,
                     float* out) {
    int b = blockIdx.x, j = threadIdx.x;
    __shared__ float sr[512];
    __shared__ float stat;
    float hv = g_h[0][b*Hn + j];
    sr[j] = hv; __syncthreads();
    for (int o = 256; o; o >>= 1) { if (j < o) sr[j] += sr[j+o]; __syncthreads(); }
    if (j == 0) stat = sr[0] / (float)Hn;
    __syncthreads();
    float mu = stat, d = hv - mu;
    __syncthreads();
    sr[j] = d*d; __syncthreads();
    for (int o = 256; o; o >>= 1) { if (j < o) sr[j] += sr[j+o]; __syncthreads(); }
    if (j == 0) stat = rsqrtf(sr[0] / (float)Hn + 1e-5f);
    __syncthreads();
    float y = d * stat * lng[j] + lnb[j];
    g_hn[b*Hn + j] = y;
    out[(size_t)Bn*Vn + b*Hn + j] = y;
}

__global__ void k_logits(const float* __restrict__ Wlm, const float* __restrict__ blm,
                         float* out) {
    __shared__ float hs[16*516];
    int bh = blockIdx.y, tid = threadIdx.x, wid = tid >> 5, lane = tid & 31;
    int b = lane & 15, vh = lane >> 4;
#pragma unroll
    for (int m = 0; m < 32; m++) {
        int idx = tid + m*256;
        int bb = idx >> 9, k = idx & 511;
        hs[bb*516 + k] = g_hn[(bh*16 + bb)*Hn + k];
    }
    __syncthreads();
    const float4* H4 = (const float4*)(hs + b*516);
#pragma unroll
    for (int s = 0; s < 4; s++) {
        int v = blockIdx.x*64 + wid*8 + s*2 + vh;
        if (v < Vn) {
            const float4* W4 = (const float4*)(Wlm + (size_t)v*Hn);
            float acc = 0.f;
#pragma unroll 8
            for (int k4 = 0; k4 < 128; k4++) {
                float4 w = W4[k4], h = H4[k4];
                acc += w.x*h.x + w.y*h.y + w.z*h.z + w.w*h.w;
            }
            out[(size_t)(bh*16 + b)*Vn + v] = acc + blm[v];
        }
    }
}

extern "C" void kernel_launch(void* const* d_in, const int* in_sizes, int n_in,
                              void* d_out, int out_size) {
    const int*   ids  = (const int*)  d_in[0];
    const float* emb  = (const float*)d_in[1];
    const float* Wq   = (const float*)d_in[2];
    const float* Wk   = (const float*)d_in[3];
    const float* Wv   = (const float*)d_in[4];
    const float* Wg   = (const float*)d_in[6];
    const float* bg   = (const float*)d_in[7];
    const float* Win  = (const float*)d_in[8];
    const float* bin  = (const float*)d_in[9];
    const float* Wh   = (const float*)d_in[10];
    const float* ltau = (const float*)d_in[11];
    const float* ldt  = (const float*)d_in[12];
    const float* Wzx  = (const float*)d_in[13];
    const float* bzx  = (const float*)d_in[14];
    const float* Wzh  = (const float*)d_in[15];
    const float* fw   = (const float*)d_in[16];
    const float* lng  = (const float*)d_in[17];
    const float* lnb  = (const float*)d_in[18];
    const float* Wlm  = (const float*)d_in[19];
    const float* blm  = (const float*)d_in[20];
    float* out = (float*)d_out;

    static int smem_set = 0;
    const int recur_smem = (16*640 + 8*32*33) * 4;   // 74,752 bytes
    if (!smem_set) {
        cudaFuncSetAttribute(k_recur, cudaFuncAttributeMaxDynamicSharedMemorySize,
                             recur_smem);
        smem_set = 1;
    }

    k_init<<<64, 256>>>();
    k_embed<<<BTn, 128>>>(ids, emb);

    dim3 gp(BTn/128, 4);
    k_proj<<<gp, 256>>>(0, Wq, nullptr, 1);   // q = phi(x Wq^T)
    k_proj<<<gp, 256>>>(1, Wk, nullptr, 1);   // k = phi(x Wk^T)
    k_proj<<<gp, 256>>>(2, Wv, nullptr, 0);   // v
    k_proj<<<gp, 256>>>(3, Wg, bg,      2);   // gate

    k_rkv<<<dim3(4, 32), 128>>>();
    k_attn<<<BTn, 256>>>();                   // x2 -> g_x (in place)

    k_proj<<<gp, 256>>>(0, Win, bin, 0);      // xin -> g_q
    k_proj<<<gp, 256>>>(1, Wzx, bzx, 0);      // xzx -> g_k
    k_prep<<<1024, 256>>>(fw, ldt, ltau);

    k_recur<<<128, 256, recur_smem>>>(Wh, Wzh);

    k_ln<<<32, 512>>>(lng, lnb, out);
    k_pe<<<1, 512>>>(out);
    k_logits<<<dim3(786, 2), 256>>>(Wlm, blm, out);
}

// round 13
// speedup vs baseline: 1.8768x; 1.1572x over previous
#include <cuda_runtime.h>
#include <math.h>

#define Bn 32
#define Tn 2048
#define Vn 50257
#define Dn 512
#define Hn 512
#define BTn (Bn*Tn)

typedef unsigned long long ull;
#define FMA2(acc, a, b) asm("fma.rn.f32x2 %0, %1, %2, %0;" : "+l"(acc) : "l"(a), "l"(b))

// ------- scratch (__device__ globals: allocation-free) -------
__device__ float g_x[(size_t)BTn*Dn];   // x, then x2 in place
__device__ float g_q[(size_t)BTn*Dn];   // q, then xin
__device__ float g_k[(size_t)BTn*Dn];   // k, then xzx
__device__ float g_v[(size_t)BTn*Dn];
__device__ float g_g[(size_t)BTn*Dn];
__device__ float g_ks[Bn*Dn];
__device__ float g_kvs[Bn*Dn];
__device__ float g_h[2][Bn*Hn];
__device__ float g_hn[Bn*Hn];
__device__ float g_fT[Hn*Hn];
__device__ float g_dt[Hn];
__device__ float g_tau[Hn];
__device__ unsigned g_barrier[8];
__device__ unsigned g_fw_nz;

__global__ void k_init() {
    int i = blockIdx.x * 256 + threadIdx.x;
    if (i < Bn*Hn) { g_h[0][i] = 0.f; g_ks[i] = 0.f; g_kvs[i] = 0.f; }
    if (i < 8) g_barrier[i] = 0u;
    if (i == 8) g_fw_nz = 0u;
}

__global__ void k_embed(const int* __restrict__ ids, const float* __restrict__ emb) {
    int bt = blockIdx.x;
    int id = ids[bt];
    ((float4*)(g_x + (size_t)bt * Dn))[threadIdx.x] =
        ((const float4*)(emb + (size_t)id * Dn))[threadIdx.x];
}

// C[m,n] = act( sum_k X[m,k]*W[n,k] + bias[n] ), X = g_x always.
// 128x128 tile, K-tile 8, 256 thr, 8x8/thread via packed fma.rn.f32x2.
__global__ __launch_bounds__(256,2) void k_proj(int osel, const float* __restrict__ W,
                                                const float* __restrict__ bias, int act) {
    float* outp = (osel==0)?g_q:(osel==1)?g_k:(osel==2)?g_v:g_g;
    __shared__ __align__(16) float As[8][132];
    __shared__ __align__(16) float Bs[8][132];
    int tid = threadIdx.x;
    int tx = tid & 15, ty = tid >> 4;
    int m0 = blockIdx.x * 128, n0 = blockIdx.y * 128;
    int lrow = tid >> 1, lcol = (tid & 1) * 4;
    const float* Ap = g_x + (size_t)(m0 + lrow) * Dn + lcol;
    const float* Bp = W   + (size_t)(n0 + lrow) * Dn + lcol;
    ull acc2[8][4];
#pragma unroll
    for (int i = 0; i < 8; i++)
#pragma unroll
        for (int jp = 0; jp < 4; jp++) acc2[i][jp] = 0ull;
    for (int kt = 0; kt < 64; kt++) {
        float4 av = *(const float4*)(Ap + kt*8);
        float4 bv = *(const float4*)(Bp + kt*8);
        __syncthreads();
        As[lcol+0][lrow]=av.x; As[lcol+1][lrow]=av.y; As[lcol+2][lrow]=av.z; As[lcol+3][lrow]=av.w;
        Bs[lcol+0][lrow]=bv.x; Bs[lcol+1][lrow]=bv.y; Bs[lcol+2][lrow]=bv.z; Bs[lcol+3][lrow]=bv.w;
        __syncthreads();
#pragma unroll
        for (int kk = 0; kk < 8; kk++) {
            float a[8];
            *(float4*)(a)   = *(const float4*)&As[kk][ty*8];
            *(float4*)(a+4) = *(const float4*)&As[kk][ty*8+4];
            ulonglong2 bA = *(const ulonglong2*)&Bs[kk][tx*8];
            ulonglong2 bB = *(const ulonglong2*)&Bs[kk][tx*8+4];
#pragma unroll
            for (int i = 0; i < 8; i++) {
                ull as_;
                asm("mov.b64 %0, {%1,%1};" : "=l"(as_) : "f"(a[i]));
                FMA2(acc2[i][0], as_, bA.x);
                FMA2(acc2[i][1], as_, bA.y);
                FMA2(acc2[i][2], as_, bB.x);
                FMA2(acc2[i][3], as_, bB.y);
            }
        }
    }
#pragma unroll
    for (int i = 0; i < 8; i++) {
        int m = m0 + ty*8 + i;
#pragma unroll
        for (int jp = 0; jp < 4; jp++) {
            int n = n0 + tx*8 + jp*2;
            float c0, c1;
            asm("mov.b64 {%0,%1}, %2;" : "=f"(c0), "=f"(c1) : "l"(acc2[i][jp]));
            if (bias) { c0 += bias[n]; c1 += bias[n+1]; }
            if (act == 1) {
                c0 = (c0 > 0.f) ? (c0 + 1.f) : __expf(c0);
                c1 = (c1 > 0.f) ? (c1 + 1.f) : __expf(c1);
            } else if (act == 2) {
                c0 = 1.f / (1.f + __expf(-c0));
                c1 = 1.f / (1.f + __expf(-c1));
            }
            *(float2*)(outp + (size_t)m * Dn + n) = make_float2(c0, c1);
        }
    }
}

__global__ void k_rkv() {
    int b = blockIdx.y, n = blockIdx.x*128 + threadIdx.x;
    const float* Kp = g_k + (size_t)b*Tn*Dn + n;
    const float* Vp = g_v + (size_t)b*Tn*Dn + n;
    float sk = 0.f, sv = 0.f;
#pragma unroll 8
    for (int t = 0; t < Tn; t++) {
        float kk = Kp[(size_t)t*Dn];
        float vv = Vp[(size_t)t*Dn];
        sk += kk; sv += kk*vv;
    }
    g_ks[b*Dn+n] = sk; g_kvs[b*Dn+n] = sv;
}

__global__ void k_attn() {
    int bt = blockIdx.x, b = bt >> 11;
    int tid = threadIdx.x, wid = tid >> 5, lane = tid & 31;
    __shared__ float sp[8][4];
    __shared__ float sf[4];
    const float* qr  = g_q + (size_t)bt*Dn;
    const float* ks  = g_ks  + b*Dn;
    const float* kvs = g_kvs + b*Dn;
    float q0 = qr[tid], q1 = qr[tid+256];
    float pn0 = q0*kvs[tid],     pd0 = q0*ks[tid];
    float pn1 = q1*kvs[tid+256], pd1 = q1*ks[tid+256];
#pragma unroll
    for (int o = 16; o; o >>= 1) {
        pn0 += __shfl_xor_sync(~0u,pn0,o); pd0 += __shfl_xor_sync(~0u,pd0,o);
        pn1 += __shfl_xor_sync(~0u,pn1,o); pd1 += __shfl_xor_sync(~0u,pd1,o);
    }
    if (lane == 0) { sp[wid][0]=pn0; sp[wid][1]=pd0; sp[wid][2]=pn1; sp[wid][3]=pd1; }
    __syncthreads();
    if (tid == 0) {
        float a=0,c=0,d=0,e=0;
        for (int w = 0; w < 8; w++) { a+=sp[w][0]; c+=sp[w][1]; d+=sp[w][2]; e+=sp[w][3]; }
        sf[0]=a; sf[1]=c; sf[2]=d; sf[3]=e;
    }
    __syncthreads();
    float s0 = sf[0] / (sf[1] + 1e-6f);
    float s1 = sf[2] / (sf[3] + 1e-6f);
    float* xr = g_x + (size_t)bt*Dn;
    const float* gr = g_g + (size_t)bt*Dn;
    float ga = gr[tid],   xa = xr[tid];
    float gb = gr[tid+256], xb = xr[tid+256];
    xr[tid]     = ga*s0 + (1.f-ga)*xa;
    xr[tid+256] = gb*s1 + (1.f-gb)*xb;
}

__global__ void k_prep(const float* __restrict__ fw, const float* __restrict__ ldt,
                       const float* __restrict__ ltau) {
    int i = blockIdx.x*256 + threadIdx.x;
    int r = i >> 9, c = i & 511;
    float v = fw[i];
    g_fT[c*Hn + r] = v;
    if (v != 0.f) atomicOr(&g_fw_nz, 1u);
    if (i < Hn) { g_dt[i] = expf(ldt[i]); g_tau[i] = expf(ltau[i]); }
}

// Persistent recurrence: 256 blocks = 32 j-chunks(16 j) x 8 batch-quarters(4 b),
// 256 thr = 8 warps, warp = 2 j-rows x 4 batches (h read shared by both j).
// 2 blocks/SM, independent barrier per batch-quarter -> barrier wait of one
// block overlaps the other block's compute. Weights in registers; h staged
// pad-swizzled (conflict-free LDS.128); fast_W handled in a rare second pass.
__global__ __launch_bounds__(256,2) void k_recur(const float* __restrict__ Wh,
                                                 const float* __restrict__ Wz) {
    extern __shared__ float sm[];
    float* hs  = sm;                       // [4][640]
    float* red = sm + 4*640;               // 8 warps x [16][33]
    float* wsF = sm + 4*640 + 8*16*33;     // [16][512] fast_W rows (use_f only)
    int bq = blockIdx.x & 7, jc = blockIdx.x >> 3;
    int tid = threadIdx.x, wid = tid >> 5, lane = tid & 31;
    unsigned use_f = g_fw_nz;

    int jA = jc*16 + wid*2;
    ull wuA[8], wuB[8], wzA[8], wzB[8];
    {
        const ull* puA = (const ull*)(Wh + (size_t)jA*Hn + lane*16);
        const ull* puB = (const ull*)(Wh + (size_t)(jA+1)*Hn + lane*16);
        const ull* pzA = (const ull*)(Wz + (size_t)jA*Hn + lane*16);
        const ull* pzB = (const ull*)(Wz + (size_t)(jA+1)*Hn + lane*16);
#pragma unroll
        for (int p = 0; p < 8; p++) {
            wuA[p]=puA[p]; wuB[p]=puB[p]; wzA[p]=pzA[p]; wzB[p]=pzB[p];
        }
    }
    if (use_f) {   // stage this block's 16 fast_W^T rows (rare path)
        const float4* s2 = (const float4*)(g_fT + (size_t)jc*16*Hn);
        float4* d2 = (float4*)wsF;
        for (int q = tid; q < 2048; q += 256) d2[q] = s2[q];
    }

    // epilogue lane mapping: even lanes <16 own (j_loc, b_loc)
    int v = lane;
    int j_loc = v >> 3, b_loc = (v >> 1) & 3;
    int jglob = jc*16 + wid*2 + j_loc;
    int bg = bq*4 + b_loc;
    bool epi = (lane < 16) && ((lane & 1) == 0);
    float dtj = 0.f, tauj = 0.f, xi = 0.f, xz = 0.f;
    const float* xin = g_q;  const float* xzx = g_k;
    if (epi) {
        dtj = g_dt[jglob]; tauj = g_tau[jglob];
        xin = g_q + (size_t)bg*Tn*Hn + jglob;
        xzx = g_k + (size_t)bg*Tn*Hn + jglob;
        xi = xin[0]; xz = xzx[0];
    }
    int lane_off = 20*lane;            // phys word of lane's k-chunk in an hs row
    int jphys = jglob + 4*(jglob >> 4);
    float* rw = red + wid*528;
    unsigned* bar = &g_barrier[bq];

    for (int t = 0; t < Tn; t++) {
        // stage 4 h rows: coalesced LDG.128 -> swizzled STS.128
        const float4* hp = (const float4*)(g_h[t & 1] + (size_t)bq*4*Hn);
#pragma unroll
        for (int m = 0; m < 2; m++) {
            int idx = tid + m*256;          // b(2b)*128 + k4(7b)
            int b = idx >> 7, k4 = idx & 127;
            float4 hv = __ldcg(hp + idx);
            *(float4*)(hs + b*640 + k4*4 + ((k4 >> 2) << 2)) = hv;
        }
        __syncthreads();

        ull au[2][4], az[2][4];
#pragma unroll
        for (int jj = 0; jj < 2; jj++)
#pragma unroll
            for (int b = 0; b < 4; b++) { au[jj][b]=0ull; az[jj][b]=0ull; }
#pragma unroll
        for (int b = 0; b < 4; b++) {
            const ulonglong2* h2 = (const ulonglong2*)(hs + b*640 + lane_off);
            ulonglong2 hA = h2[0], hB = h2[1], hC = h2[2], hD = h2[3];
            FMA2(au[0][b],wuA[0],hA.x); FMA2(az[0][b],wzA[0],hA.x);
            FMA2(au[1][b],wuB[0],hA.x); FMA2(az[1][b],wzB[0],hA.x);
            FMA2(au[0][b],wuA[1],hA.y); FMA2(az[0][b],wzA[1],hA.y);
            FMA2(au[1][b],wuB[1],hA.y); FMA2(az[1][b],wzB[1],hA.y);
            FMA2(au[0][b],wuA[2],hB.x); FMA2(az[0][b],wzA[2],hB.x);
            FMA2(au[1][b],wuB[2],hB.x); FMA2(az[1][b],wzB[2],hB.x);
            FMA2(au[0][b],wuA[3],hB.y); FMA2(az[0][b],wzA[3],hB.y);
            FMA2(au[1][b],wuB[3],hB.y); FMA2(az[1][b],wzB[3],hB.y);
            FMA2(au[0][b],wuA[4],hC.x); FMA2(az[0][b],wzA[4],hC.x);
            FMA2(au[1][b],wuB[4],hC.x); FMA2(az[1][b],wzB[4],hC.x);
            FMA2(au[0][b],wuA[5],hC.y); FMA2(az[0][b],wzA[5],hC.y);
            FMA2(au[1][b],wuB[5],hC.y); FMA2(az[1][b],wzB[5],hC.y);
            FMA2(au[0][b],wuA[6],hD.x); FMA2(az[0][b],wzA[6],hD.x);
            FMA2(au[1][b],wuB[6],hD.x); FMA2(az[1][b],wzB[6],hD.x);
            FMA2(au[0][b],wuA[7],hD.y); FMA2(az[0][b],wzA[7],hD.y);
            FMA2(au[1][b],wuB[7],hD.y); FMA2(az[1][b],wzB[7],hD.y);
        }

        // transpose-reduce: value idx = j*8 + b*2 + mat  (16 rows)
#pragma unroll
        for (int jj = 0; jj < 2; jj++)
#pragma unroll
            for (int b = 0; b < 4; b++) {
                unsigned lo, hi;
                asm("mov.b64 {%0,%1}, %2;" : "=r"(lo), "=r"(hi) : "l"(au[jj][b]));
                rw[(jj*8 + b*2 + 0)*33 + lane] = __uint_as_float(lo) + __uint_as_float(hi);
                asm("mov.b64 {%0,%1}, %2;" : "=r"(lo), "=r"(hi) : "l"(az[jj][b]));
                rw[(jj*8 + b*2 + 1)*33 + lane] = __uint_as_float(lo) + __uint_as_float(hi);
            }
        __syncwarp();
        float s = 0.f;
        if (lane < 16) {
#pragma unroll
            for (int i = 0; i < 32; i++) s += rw[lane*33 + i];
        }
        float saz = __shfl_xor_sync(~0u, s, 1);   // even lanes: s=au, saz=az

        float sfv = 0.f;
        if (use_f) {   // rare second pass: fast_W from SMEM
            ull af[2][4];
#pragma unroll
            for (int jj = 0; jj < 2; jj++)
#pragma unroll
                for (int b = 0; b < 4; b++) af[jj][b] = 0ull;
#pragma unroll
            for (int b = 0; b < 4; b++) {
                const ulonglong2* h2 = (const ulonglong2*)(hs + b*640 + lane_off);
                ulonglong2 hA = h2[0], hB = h2[1], hC = h2[2], hD = h2[3];
#pragma unroll
                for (int jj = 0; jj < 2; jj++) {
                    const ull* wf = (const ull*)(wsF + (wid*2 + jj)*512 + lane*16);
                    FMA2(af[jj][b], wf[0], hA.x); FMA2(af[jj][b], wf[1], hA.y);
                    FMA2(af[jj][b], wf[2], hB.x); FMA2(af[jj][b], wf[3], hB.y);
                    FMA2(af[jj][b], wf[4], hC.x); FMA2(af[jj][b], wf[5], hC.y);
                    FMA2(af[jj][b], wf[6], hD.x); FMA2(af[jj][b], wf[7], hD.y);
                }
            }
            __syncwarp();
#pragma unroll
            for (int jj = 0; jj < 2; jj++)
#pragma unroll
                for (int b = 0; b < 4; b++) {
                    unsigned lo, hi;
                    asm("mov.b64 {%0,%1}, %2;" : "=r"(lo), "=r"(hi) : "l"(af[jj][b]));
                    rw[(jj*4 + b)*33 + lane] = __uint_as_float(lo) + __uint_as_float(hi);
                }
            __syncwarp();
            float sa = 0.f;
            if (lane < 8) {
#pragma unroll
                for (int i = 0; i < 32; i++) sa += rw[lane*33 + i];
            }
            int src = ((v >> 3) << 2) | ((v >> 1) & 3);
            sfv = __shfl_sync(~0u, sa, src);
        }

        if (epi) {
            float h  = hs[b_loc*640 + jphys];
            float u  = xi + s;
            float f  = tanhf(u);
            float hl = h + dtj*(f - tauj*h);
            float z  = 1.f/(1.f+__expf(-(xz + saz)));
            float hn2 = (1.f - z)*h + z*hl + sfv;
            __stcg(&g_h[(t & 1) ^ 1][(size_t)bg*Hn + jglob], hn2);
            if (t + 1 < Tn) {
                xi = xin[(size_t)(t+1)*Hn];
                xz = xzx[(size_t)(t+1)*Hn];
            }
        }
        // 32-block grid barrier for this batch-quarter
        __syncthreads();
        if (tid == 0) {
            unsigned target = 32u * (unsigned)(t + 1);
            asm volatile("red.release.gpu.add.u32 [%0], %1;"
                         :: "l"(bar), "r"(1u) : "memory");
            unsigned vv;
            do {
                asm volatile("ld.relaxed.gpu.u32 %0, [%1];" : "=r"(vv) : "l"(bar));
            } while (vv < target);
            asm volatile("fence.acq_rel.gpu;" ::: "memory");
        }
        __syncthreads();
    }
}

__global__ void k_pe(float* out) {
    __shared__ float sr[512];
    float s = 0.f;
    for (int i = threadIdx.x; i < Bn*Hn; i += 512) {
        float d = g_h[0][i] - g_h[1][i]; s += d*d;
    }
    sr[threadIdx.x] = s; __syncthreads();
    for (int o = 256; o; o >>= 1) {
        if (threadIdx.x < o) sr[threadIdx.x] += sr[threadIdx.x + o];
        __syncthreads();
    }
    if (threadIdx.x == 0)
        out[(size_t)Bn*Vn + (size_t)Bn*Hn] = sqrtf(sr[0] / (float)(Bn*Hn));
}

__global__ void k_ln(const float* __restrict__ lng, const float* __restrict__ lnb,
                     float* out) {
    int b = blockIdx.x, j = threadIdx.x;
    __shared__ float sr[512];
    __shared__ float stat;
    float hv = g_h[0][b*Hn + j];
    sr[j] = hv; __syncthreads();
    for (int o = 256; o; o >>= 1) { if (j < o) sr[j] += sr[j+o]; __syncthreads(); }
    if (j == 0) stat = sr[0] / (float)Hn;
    __syncthreads();
    float mu = stat, d = hv - mu;
    __syncthreads();
    sr[j] = d*d; __syncthreads();
    for (int o = 256; o; o >>= 1) { if (j < o) sr[j] += sr[j+o]; __syncthreads(); }
    if (j == 0) stat = rsqrtf(sr[0] / (float)Hn + 1e-5f);
    __syncthreads();
    float y = d * stat * lng[j] + lnb[j];
    g_hn[b*Hn + j] = y;
    out[(size_t)Bn*Vn + b*Hn + j] = y;
}

__global__ void k_logits(const float* __restrict__ Wlm, const float* __restrict__ blm,
                         float* out) {
    __shared__ float hs[16*516];
    int bh = blockIdx.y, tid = threadIdx.x, wid = tid >> 5, lane = tid & 31;
    int b = lane & 15, vh = lane >> 4;
#pragma unroll
    for (int m = 0; m < 32; m++) {
        int idx = tid + m*256;
        int bb = idx >> 9, k = idx & 511;
        hs[bb*516 + k] = g_hn[(bh*16 + bb)*Hn + k];
    }
    __syncthreads();
    const float4* H4 = (const float4*)(hs + b*516);
#pragma unroll
    for (int s = 0; s < 4; s++) {
        int v = blockIdx.x*64 + wid*8 + s*2 + vh;
        if (v < Vn) {
            const float4* W4 = (const float4*)(Wlm + (size_t)v*Hn);
            float acc = 0.f;
#pragma unroll 8
            for (int k4 = 0; k4 < 128; k4++) {
                float4 w = W4[k4], h = H4[k4];
                acc += w.x*h.x + w.y*h.y + w.z*h.z + w.w*h.w;
            }
            out[(size_t)(bh*16 + b)*Vn + v] = acc + blm[v];
        }
    }
}

extern "C" void kernel_launch(void* const* d_in, const int* in_sizes, int n_in,
                              void* d_out, int out_size) {
    const int*   ids  = (const int*)  d_in[0];
    const float* emb  = (const float*)d_in[1];
    const float* Wq   = (const float*)d_in[2];
    const float* Wk   = (const float*)d_in[3];
    const float* Wv   = (const float*)d_in[4];
    const float* Wg   = (const float*)d_in[6];
    const float* bg   = (const float*)d_in[7];
    const float* Win  = (const float*)d_in[8];
    const float* bin  = (const float*)d_in[9];
    const float* Wh   = (const float*)d_in[10];
    const float* ltau = (const float*)d_in[11];
    const float* ldt  = (const float*)d_in[12];
    const float* Wzx  = (const float*)d_in[13];
    const float* bzx  = (const float*)d_in[14];
    const float* Wzh  = (const float*)d_in[15];
    const float* fw   = (const float*)d_in[16];
    const float* lng  = (const float*)d_in[17];
    const float* lnb  = (const float*)d_in[18];
    const float* Wlm  = (const float*)d_in[19];
    const float* blm  = (const float*)d_in[20];
    float* out = (float*)d_out;

    static int smem_set = 0;
    const int recur_smem = (4*640 + 8*16*33 + 16*512) * 4;   // 59,904 bytes
    if (!smem_set) {
        cudaFuncSetAttribute(k_recur, cudaFuncAttributeMaxDynamicSharedMemorySize,
                             recur_smem);
        smem_set = 1;
    }

    k_init<<<64, 256>>>();
    k_embed<<<BTn, 128>>>(ids, emb);

    dim3 gp(BTn/128, 4);
    k_proj<<<gp, 256>>>(0, Wq, nullptr, 1);   // q = phi(x Wq^T)
    k_proj<<<gp, 256>>>(1, Wk, nullptr, 1);   // k = phi(x Wk^T)
    k_proj<<<gp, 256>>>(2, Wv, nullptr, 0);   // v
    k_proj<<<gp, 256>>>(3, Wg, bg,      2);   // gate

    k_rkv<<<dim3(4, 32), 128>>>();
    k_attn<<<BTn, 256>>>();                   // x2 -> g_x (in place)

    k_proj<<<gp, 256>>>(0, Win, bin, 0);      // xin -> g_q
    k_proj<<<gp, 256>>>(1, Wzx, bzx, 0);      // xzx -> g_k
    k_prep<<<1024, 256>>>(fw, ldt, ltau);

    k_recur<<<256, 256, recur_smem>>>(Wh, Wzh);

    k_ln<<<32, 512>>>(lng, lnb, out);
    k_pe<<<1, 512>>>(out);
    k_logits<<<dim3(786, 2), 256>>>(Wlm, blm, out);
}